// round 2
// baseline (speedup 1.0000x reference)
#include <cuda_runtime.h>
#include <math.h>

// ---------------------------------------------------------------------------
// Problem constants
// ---------------------------------------------------------------------------
#define NB    32
#define C_ST  2048
#define C_LT  2048
#define LAT   512
#define SS    512
#define LL    2048
#define LN_EPS 1e-5f

// ---------------------------------------------------------------------------
// Scratch (device globals; no runtime allocation allowed)
// ---------------------------------------------------------------------------
__device__ float g_theta [ (long)NB * LAT * SS ];   //  33.5 MB  (also reused for normed output)
__device__ float g_phi   [ (long)NB * LAT * LL ];   // 134 MB
__device__ float g_gbuf  [ (long)NB * LAT * LL ];   // 134 MB
__device__ float g_scores[ (long)NB * SS  * LL ];   // 134 MB
__device__ float g_att   [ (long)NB * LAT * SS ];   //  33.5 MB
__device__ float2 g_stats[ NB ];                    // (mu, inv_std)

// ---------------------------------------------------------------------------
// Generic batched GEMM:  C[b] = alpha * A[b] * B[b] + bias
//   A(m,k) = AK ? A[m*lda + k] : A[k*lda + m]
//   B(k,n) = BN ? B[k*ldb + n] : B[n*ldb + k]
//   C(m,n) = C[m*ldc + n]
// Tiles: BM=BN=128, BK=16, 256 threads, 8x8 per-thread micro-tile.
// All dims assumed divisible by 128 (M,N) and 16 (K). lda/ldb multiples of 4.
// ---------------------------------------------------------------------------
template<bool AK, bool BN>
__global__ __launch_bounds__(256)
void gemm_kernel(const float* __restrict__ A, const float* __restrict__ B,
                 float* __restrict__ C,
                 int M, int N, int K, int lda, int ldb, int ldc,
                 long sA, long sB, long sC,
                 float alpha, const float* __restrict__ bias)
{
    __shared__ float As[16][128];
    __shared__ float Bs[16][128];

    const int b  = blockIdx.z;
    const float* Ab = A + (long)b * sA;
    const float* Bb = B + (long)b * sB;
    float*       Cb = C + (long)b * sC;

    const int m0 = blockIdx.y * 128;
    const int n0 = blockIdx.x * 128;
    const int tid = threadIdx.x;
    const int tx = tid & 15;        // 0..15 -> n micro
    const int ty = tid >> 4;        // 0..15 -> m micro

    float acc[8][8];
#pragma unroll
    for (int i = 0; i < 8; ++i)
#pragma unroll
        for (int j = 0; j < 8; ++j) acc[i][j] = 0.f;

    for (int kt = 0; kt < K; kt += 16) {
        // ---- load A tile into As[k][m] ----
        if (AK) {
            // A contiguous in k: float4 along k, transpose into smem
#pragma unroll
            for (int i = 0; i < 2; ++i) {
                int idx = tid + i * 256;            // 0..511 float4 slots
                int m  = idx >> 2;                  // 0..127
                int kq = (idx & 3) << 2;            // 0,4,8,12
                float4 v = *reinterpret_cast<const float4*>(
                    Ab + (long)(m0 + m) * lda + kt + kq);
                As[kq + 0][m] = v.x; As[kq + 1][m] = v.y;
                As[kq + 2][m] = v.z; As[kq + 3][m] = v.w;
            }
        } else {
            // A contiguous in m: straight coalesced scalar loads
#pragma unroll
            for (int i = 0; i < 8; ++i) {
                int idx = tid + i * 256;            // 0..2047
                int k = idx >> 7;
                int m = idx & 127;
                As[k][m] = Ab[(long)(kt + k) * lda + m0 + m];
            }
        }
        // ---- load B tile into Bs[k][n] ----
        if (BN) {
#pragma unroll
            for (int i = 0; i < 8; ++i) {
                int idx = tid + i * 256;
                int k = idx >> 7;
                int n = idx & 127;
                Bs[k][n] = Bb[(long)(kt + k) * ldb + n0 + n];
            }
        } else {
            // B contiguous in k: float4 along k, transpose
#pragma unroll
            for (int i = 0; i < 2; ++i) {
                int idx = tid + i * 256;
                int n  = idx >> 2;
                int kq = (idx & 3) << 2;
                float4 v = *reinterpret_cast<const float4*>(
                    Bb + (long)(n0 + n) * ldb + kt + kq);
                Bs[kq + 0][n] = v.x; Bs[kq + 1][n] = v.y;
                Bs[kq + 2][n] = v.z; Bs[kq + 3][n] = v.w;
            }
        }
        __syncthreads();

#pragma unroll
        for (int k = 0; k < 16; ++k) {
            float ra[8], rb[8];
            float4 a0 = *reinterpret_cast<const float4*>(&As[k][ty * 8]);
            float4 a1 = *reinterpret_cast<const float4*>(&As[k][ty * 8 + 4]);
            float4 b0 = *reinterpret_cast<const float4*>(&Bs[k][tx * 8]);
            float4 b1 = *reinterpret_cast<const float4*>(&Bs[k][tx * 8 + 4]);
            ra[0]=a0.x; ra[1]=a0.y; ra[2]=a0.z; ra[3]=a0.w;
            ra[4]=a1.x; ra[5]=a1.y; ra[6]=a1.z; ra[7]=a1.w;
            rb[0]=b0.x; rb[1]=b0.y; rb[2]=b0.z; rb[3]=b0.w;
            rb[4]=b1.x; rb[5]=b1.y; rb[6]=b1.z; rb[7]=b1.w;
#pragma unroll
            for (int i = 0; i < 8; ++i)
#pragma unroll
                for (int j = 0; j < 8; ++j)
                    acc[i][j] += ra[i] * rb[j];
        }
        __syncthreads();
    }

    // ---- epilogue ----
#pragma unroll
    for (int i = 0; i < 8; ++i) {
        int m = m0 + ty * 8 + i;
        float bv = bias ? bias[m] : 0.f;
        float* crow = Cb + (long)m * ldc + n0 + tx * 8;
#pragma unroll
        for (int j = 0; j < 8; j += 4) {
            float4 v;
            v.x = acc[i][j + 0] * alpha + bv;
            v.y = acc[i][j + 1] * alpha + bv;
            v.z = acc[i][j + 2] * alpha + bv;
            v.w = acc[i][j + 3] * alpha + bv;
            *reinterpret_cast<float4*>(crow + j) = v;
        }
    }
}

// ---------------------------------------------------------------------------
// Softmax over last dim (L=2048), one block (256 threads) per row, in-place.
// ---------------------------------------------------------------------------
__global__ __launch_bounds__(256)
void softmax_kernel(float* __restrict__ x)
{
    const long row = blockIdx.x;
    float* p = x + row * (long)LL;
    const int tid = threadIdx.x;

    float v[8];
#pragma unroll
    for (int i = 0; i < 8; ++i) v[i] = p[tid + i * 256];

    float m = v[0];
#pragma unroll
    for (int i = 1; i < 8; ++i) m = fmaxf(m, v[i]);
#pragma unroll
    for (int o = 16; o > 0; o >>= 1) m = fmaxf(m, __shfl_xor_sync(0xffffffffu, m, o));
    __shared__ float sm[8];
    if ((tid & 31) == 0) sm[tid >> 5] = m;
    __syncthreads();
    float mx = sm[0];
#pragma unroll
    for (int i = 1; i < 8; ++i) mx = fmaxf(mx, sm[i]);

    float s = 0.f;
#pragma unroll
    for (int i = 0; i < 8; ++i) { v[i] = __expf(v[i] - mx); s += v[i]; }
#pragma unroll
    for (int o = 16; o > 0; o >>= 1) s += __shfl_xor_sync(0xffffffffu, s, o);
    __shared__ float ss[8];
    if ((tid & 31) == 0) ss[tid >> 5] = s;
    __syncthreads();
    float tot = 0.f;
#pragma unroll
    for (int i = 0; i < 8; ++i) tot += ss[i];
    float inv = 1.f / tot;
#pragma unroll
    for (int i = 0; i < 8; ++i) p[tid + i * 256] = v[i] * inv;
}

// ---------------------------------------------------------------------------
// LayerNorm stats: one block per batch, reduce 512*512 elements.
// ---------------------------------------------------------------------------
__global__ __launch_bounds__(512)
void stats_kernel(const float* __restrict__ att, float2* __restrict__ stats)
{
    const int n = blockIdx.x;
    const float* x = att + (long)n * LAT * SS;
    const int tid = threadIdx.x;
    float s = 0.f, s2 = 0.f;
    for (int i = tid; i < LAT * SS; i += 512) {
        float v = x[i];
        s += v; s2 += v * v;
    }
#pragma unroll
    for (int o = 16; o > 0; o >>= 1) {
        s  += __shfl_xor_sync(0xffffffffu, s,  o);
        s2 += __shfl_xor_sync(0xffffffffu, s2, o);
    }
    __shared__ float rs[16], rs2[16];
    if ((tid & 31) == 0) { rs[tid >> 5] = s; rs2[tid >> 5] = s2; }
    __syncthreads();
    if (tid == 0) {
        float S = 0.f, S2 = 0.f;
#pragma unroll
        for (int i = 0; i < 16; ++i) { S += rs[i]; S2 += rs2[i]; }
        const float invM = 1.f / (float)(LAT * SS);
        float mu = S * invM;
        float var = S2 * invM - mu * mu;
        stats[n] = make_float2(mu, rsqrtf(var + LN_EPS));
    }
}

// ---------------------------------------------------------------------------
// Affine (LayerNorm apply) + ReLU:  y = relu((x-mu)*rstd*ln_w + ln_b)
// x,y layout (n, LAT, SS); ln_w/ln_b layout (LAT, SS).
// ---------------------------------------------------------------------------
__global__ __launch_bounds__(256)
void affine_relu_kernel(const float* __restrict__ x,
                        const float* __restrict__ ln_w,
                        const float* __restrict__ ln_b,
                        const float2* __restrict__ stats,
                        float* __restrict__ y)
{
    long idx4 = ((long)blockIdx.x * 256 + threadIdx.x);
    long idx = idx4 * 4;                  // element index
    int n  = (int)(idx >> 18);            // / (512*512)
    int cs = (int)(idx & 262143);
    float2 st = stats[n];
    float4 xv = *reinterpret_cast<const float4*>(x + idx);
    float4 wv = *reinterpret_cast<const float4*>(ln_w + cs);
    float4 bv = *reinterpret_cast<const float4*>(ln_b + cs);
    float4 o;
    o.x = fmaxf((xv.x - st.x) * st.y * wv.x + bv.x, 0.f);
    o.y = fmaxf((xv.y - st.x) * st.y * wv.y + bv.y, 0.f);
    o.z = fmaxf((xv.z - st.x) * st.y * wv.z + bv.z, 0.f);
    o.w = fmaxf((xv.w - st.x) * st.y * wv.w + bv.w, 0.f);
    *reinterpret_cast<float4*>(y + idx) = o;
}

// ---------------------------------------------------------------------------
// Launch
// ---------------------------------------------------------------------------
extern "C" void kernel_launch(void* const* d_in, const int* in_sizes, int n_in,
                              void* d_out, int out_size)
{
    const float* st_feat = (const float*)d_in[0];   // (N, C_ST, S)
    const float* lt_feat = (const float*)d_in[1];   // (N, C_LT, L)
    const float* w_st    = (const float*)d_in[2];   // (LAT, C_ST)
    const float* b_st    = (const float*)d_in[3];
    const float* w_lt    = (const float*)d_in[4];   // (LAT, C_LT)
    const float* b_lt    = (const float*)d_in[5];
    const float* w_g     = (const float*)d_in[6];   // (LAT, C_LT)
    const float* b_g     = (const float*)d_in[7];
    const float* ln_w    = (const float*)d_in[8];   // (LAT, S)
    const float* ln_b    = (const float*)d_in[9];
    const float* w_out   = (const float*)d_in[10];  // (C_ST, LAT)
    const float* b_out   = (const float*)d_in[11];
    float* out = (float*)d_out;                     // (N, C_ST, S)

    float *theta, *phi, *gbuf, *scores, *att;
    float2* stats;
    cudaGetSymbolAddress((void**)&theta,  g_theta);
    cudaGetSymbolAddress((void**)&phi,    g_phi);
    cudaGetSymbolAddress((void**)&gbuf,   g_gbuf);
    cudaGetSymbolAddress((void**)&scores, g_scores);
    cudaGetSymbolAddress((void**)&att,    g_att);
    cudaGetSymbolAddress((void**)&stats,  g_stats);

    const float inv_sqrt_lat = 0.044194173824159216f;  // 1/sqrt(512)
    dim3 blk(256);

    // 1) theta[n] = w_st @ st[n] + b_st          (LAT x S, K=C_ST)
    gemm_kernel<true, true><<<dim3(SS/128, LAT/128, NB), blk>>>(
        w_st, st_feat, theta, LAT, SS, C_ST, C_ST, SS, SS,
        0L, (long)C_ST * SS, (long)LAT * SS, 1.f, b_st);

    // 2) phi[n] = w_lt @ lt[n] + b_lt            (LAT x L, K=C_LT)
    gemm_kernel<true, true><<<dim3(LL/128, LAT/128, NB), blk>>>(
        w_lt, lt_feat, phi, LAT, LL, C_LT, C_LT, LL, LL,
        0L, (long)C_LT * LL, (long)LAT * LL, 1.f, b_lt);

    // 3) g[n] = w_g @ lt[n] + b_g                (LAT x L, K=C_LT)
    gemm_kernel<true, true><<<dim3(LL/128, LAT/128, NB), blk>>>(
        w_g, lt_feat, gbuf, LAT, LL, C_LT, C_LT, LL, LL,
        0L, (long)C_LT * LL, (long)LAT * LL, 1.f, b_g);

    // 4) scores[n] = (theta[n]^T @ phi[n]) / sqrt(LAT)     (S x L, K=LAT)
    gemm_kernel<false, true><<<dim3(LL/128, SS/128, NB), blk>>>(
        theta, phi, scores, SS, LL, LAT, SS, LL, LL,
        (long)LAT * SS, (long)LAT * LL, (long)SS * LL, inv_sqrt_lat, nullptr);

    // 5) softmax over L, per (n, s) row
    softmax_kernel<<<NB * SS, blk>>>(scores);

    // 6) att[n] = g[n] @ p[n]^T                  (LAT x S, K=L)
    gemm_kernel<true, false><<<dim3(SS/128, LAT/128, NB), blk>>>(
        gbuf, scores, att, LAT, SS, LL, LL, LL, SS,
        (long)LAT * LL, (long)SS * LL, (long)LAT * SS, 1.f, nullptr);

    // 7) LayerNorm stats per batch
    stats_kernel<<<NB, 512>>>(att, stats);

    // 8) normalize + affine + relu  -> reuse theta buffer
    {
        long total4 = (long)NB * LAT * SS / 4;       // 8,388,608 / 4 elems? (n*262144/4)
        int grid = (int)(total4 / 256);
        affine_relu_kernel<<<grid, blk>>>(att, ln_w, ln_b, stats, theta);
    }

    // 9) out[n] = w_out @ normed[n] + b_out      (C_ST x S, K=LAT)
    gemm_kernel<true, true><<<dim3(SS/128, C_ST/128, NB), blk>>>(
        w_out, theta, out, C_ST, SS, LAT, LAT, SS, SS,
        0L, (long)LAT * SS, (long)C_ST * SS, 1.f, b_out);
}

// round 4
// speedup vs baseline: 2.9774x; 2.9774x over previous
#include <cuda_runtime.h>
#include <cuda_bf16.h>
#include <cstdint>
#include <math.h>

// ---------------------------------------------------------------------------
// Problem constants
// ---------------------------------------------------------------------------
#define NB    32
#define C_ST  2048
#define C_LT  2048
#define LAT   512
#define SS    512
#define LL    2048
#define LN_EPS 1e-5f

typedef long long ll;
typedef __nv_bfloat16 bf16;

// ---------------------------------------------------------------------------
// Scratch pool (single __device__ global; offsets in bytes, 256-aligned)
// ---------------------------------------------------------------------------
static constexpr ll SZ_STT   = (ll)NB * SS  * C_ST * 2;   // one bf16 array
static constexpr ll SZ_LTT   = (ll)NB * LL  * C_LT * 2;
static constexpr ll SZ_THETA = (ll)NB * SS  * LAT  * 2;
static constexpr ll SZ_PHI   = (ll)NB * LL  * LAT  * 2;
static constexpr ll SZ_G     = (ll)NB * LAT * LL   * 2;
static constexpr ll SZ_SCORE = (ll)NB * SS  * LL   * 4;   // fp32
static constexpr ll SZ_P     = (ll)NB * SS  * LL   * 2;
static constexpr ll SZ_ATT   = (ll)NB * SS  * LAT  * 4;   // fp32
static constexpr ll SZ_Y     = (ll)NB * SS  * LAT  * 2;
static constexpr ll SZ_W     = (ll)LAT * C_ST * 2;        // each weight bf16 array
static constexpr ll SZ_LN    = (ll)LAT * SS * 4;          // transposed ln param fp32

static constexpr ll O_STT_HI   = 0;
static constexpr ll O_STT_LO   = O_STT_HI   + SZ_STT;
static constexpr ll O_LTT_HI   = O_STT_LO   + SZ_STT;
static constexpr ll O_LTT_LO   = O_LTT_HI   + SZ_LTT;
static constexpr ll O_THETA_HI = O_LTT_LO   + SZ_LTT;
static constexpr ll O_THETA_LO = O_THETA_HI + SZ_THETA;
static constexpr ll O_PHI_HI   = O_THETA_LO + SZ_THETA;
static constexpr ll O_PHI_LO   = O_PHI_HI   + SZ_PHI;
static constexpr ll O_G_HI     = O_PHI_LO   + SZ_PHI;
static constexpr ll O_G_LO     = O_G_HI     + SZ_G;
static constexpr ll O_SCORE    = O_G_LO     + SZ_G;
static constexpr ll O_P_HI     = O_SCORE    + SZ_SCORE;
static constexpr ll O_P_LO     = O_P_HI     + SZ_P;
static constexpr ll O_ATT      = O_P_LO     + SZ_P;
static constexpr ll O_Y_HI     = O_ATT      + SZ_ATT;
static constexpr ll O_Y_LO     = O_Y_HI     + SZ_Y;
static constexpr ll O_WST_HI   = O_Y_LO     + SZ_Y;
static constexpr ll O_WST_LO   = O_WST_HI   + SZ_W;
static constexpr ll O_WLT_HI   = O_WST_LO   + SZ_W;
static constexpr ll O_WLT_LO   = O_WLT_HI   + SZ_W;
static constexpr ll O_WG_HI    = O_WLT_LO   + SZ_W;
static constexpr ll O_WG_LO    = O_WG_HI    + SZ_W;
static constexpr ll O_WOUT_HI  = O_WG_LO    + SZ_W;
static constexpr ll O_WOUT_LO  = O_WOUT_HI  + SZ_W;
static constexpr ll O_LNW_T    = O_WOUT_LO  + SZ_W;
static constexpr ll O_LNB_T    = O_LNW_T    + SZ_LN;
static constexpr ll O_STATS    = O_LNB_T    + SZ_LN;
static constexpr ll POOL_BYTES = O_STATS + 256;

__device__ __align__(256) unsigned char g_pool[POOL_BYTES];

// ---------------------------------------------------------------------------
// PTX helpers (sm_80-compatible path: ldmatrix + mma.sync + cp.async)
// ---------------------------------------------------------------------------
__device__ __forceinline__ uint32_t smem_u32(const void* p) {
    uint32_t a;
    asm("{ .reg .u64 t; cvta.to.shared.u64 t, %1; cvt.u32.u64 %0, t; }"
        : "=r"(a) : "l"(p));
    return a;
}
__device__ __forceinline__ void cpa16(uint32_t s, const void* g) {
    asm volatile("cp.async.cg.shared.global [%0], [%1], 16;" :: "r"(s), "l"(g) : "memory");
}
#define CP_COMMIT asm volatile("cp.async.commit_group;" ::: "memory")
#define CP_WAIT1  asm volatile("cp.async.wait_group 1;" ::: "memory")
#define CP_WAIT0  asm volatile("cp.async.wait_group 0;" ::: "memory")

#define LDSM4(r, addr) \
    asm volatile("ldmatrix.sync.aligned.m8n8.x4.shared.b16 {%0,%1,%2,%3}, [%4];" \
        : "=r"((r)[0]), "=r"((r)[1]), "=r"((r)[2]), "=r"((r)[3]) : "r"(addr))

#define MMA16816(d, a, b0, b1) \
    asm volatile("mma.sync.aligned.m16n8k16.row.col.f32.bf16.bf16.f32 " \
        "{%0,%1,%2,%3}, {%4,%5,%6,%7}, {%8,%9}, {%0,%1,%2,%3};" \
        : "+f"((d)[0]), "+f"((d)[1]), "+f"((d)[2]), "+f"((d)[3]) \
        : "r"((a)[0]), "r"((a)[1]), "r"((a)[2]), "r"((a)[3]), "r"(b0), "r"(b1))

__device__ __forceinline__ uint32_t pack_bf(bf16 a, bf16 b) {
    return (uint32_t)__bfloat16_as_ushort(a) | ((uint32_t)__bfloat16_as_ushort(b) << 16);
}

// ---------------------------------------------------------------------------
// Tensor-core GEMM (mma.sync bf16, split hi/lo 3-term):
//   C(m,n) = alpha * sum_k (Ahi+Alo)(m,k)*(Bhi+Blo)(n,k) + bias   [lo*lo dropped]
//   A, B K-major (lda=ldb=K). Tile M=128, N=128, K-chunk 64, 3-stage cp.async.
//   OUT=0: fp32 to Cf.  OUT=1: split hi/lo bf16 to Chi/Clo.
// ---------------------------------------------------------------------------
static constexpr int STAGE_BYTES = 65536;      // Ahi16K Alo16K Bhi16K Blo16K
static constexpr int STAGES      = 3;
static constexpr int SMEM_TOTAL  = STAGES * STAGE_BYTES;   // 196608

template <int OUT>
__global__ __launch_bounds__(256) void mma_gemm(
    const bf16* __restrict__ Ahi, const bf16* __restrict__ Alo,
    const bf16* __restrict__ Bhi, const bf16* __restrict__ Blo,
    float* __restrict__ Cf, bf16* __restrict__ Chi, bf16* __restrict__ Clo,
    int K, int ldc, ll sA, ll sB, ll sC,
    float alpha, const float* __restrict__ bias, int bias_per_n)
{
    extern __shared__ __align__(1024) char smem[];
    const uint32_t sb = smem_u32(smem);
    const int tid  = threadIdx.x;
    const int wid  = tid >> 5, lane = tid & 31;
    const ll  b    = blockIdx.z;
    const int m0   = blockIdx.y << 7;
    const int n0   = blockIdx.x << 7;

    const bf16* Ah = Ahi + b * sA;
    const bf16* Al = Alo + b * sA;
    const bf16* Bh = Bhi + b * sB;
    const bf16* Bl = Blo + b * sB;

    const int C = K >> 6;

    auto load_chunk = [&](int ct, int stg) {
        const uint32_t base = sb + stg * STAGE_BYTES;
        const int kt = ct << 6;
#pragma unroll
        for (int i = 0; i < 4; ++i) {           // A: 128 rows x 128B (each half)
            int idx = tid + (i << 8);
            int row = idx >> 3, seg = idx & 7;
            ll  go  = (ll)(m0 + row) * K + kt + (seg << 3);
            uint32_t so = (uint32_t)((row << 7) + (seg << 4));
            so ^= (so >> 3) & 0x70;
            cpa16(base + so,         Ah + go);
            cpa16(base + 16384 + so, Al + go);
        }
#pragma unroll
        for (int i = 0; i < 4; ++i) {           // B: 128 rows x 128B (each half)
            int idx = tid + (i << 8);
            int row = idx >> 3, seg = idx & 7;
            ll  go  = (ll)(n0 + row) * K + kt + (seg << 3);
            uint32_t so = (uint32_t)((row << 7) + (seg << 4));
            so ^= (so >> 3) & 0x70;
            cpa16(base + 32768 + so, Bh + go);
            cpa16(base + 49152 + so, Bl + go);
        }
    };

    load_chunk(0, 0); CP_COMMIT;
    load_chunk(1, 1); CP_COMMIT;

    // warp tiling: 4 (m) x 2 (n); each warp 32(m) x 64(n)
    const int wm = wid >> 1, wn = wid & 1;
    float acc[2][8][4];
#pragma unroll
    for (int i = 0; i < 2; ++i)
#pragma unroll
        for (int j = 0; j < 8; ++j)
#pragma unroll
            for (int q = 0; q < 4; ++q) acc[i][j][q] = 0.f;

    // ldmatrix lane addressing (within tile, before swizzle)
    const uint32_t a_row = (uint32_t)(wm * 32 + (lane & 15));
    const uint32_t a_sb  = (uint32_t)(lane >> 4);            // +seg for k8-15
    const uint32_t b_row = (uint32_t)(wn * 64 + ((lane >> 4) << 3) + (lane & 7));
    const uint32_t b_sb  = (uint32_t)((lane >> 3) & 1);

    for (int ct = 0; ct < C; ++ct) {
        if (ct == C - 1) { CP_WAIT0; } else { CP_WAIT1; }
        __syncthreads();
        const uint32_t sbase = sb + (ct % 3) * STAGE_BYTES;

#pragma unroll
        for (int s = 0; s < 4; ++s) {           // 4 x k16 per chunk
            uint32_t ah[2][4], al[2][4];
#pragma unroll
            for (int mt = 0; mt < 2; ++mt) {
                uint32_t row = a_row + mt * 16;
                uint32_t seg = (uint32_t)(s * 2) + a_sb;
                uint32_t off = (row << 7) + (seg << 4);
                off ^= (off >> 3) & 0x70;
                LDSM4(ah[mt], sbase + off);
                LDSM4(al[mt], sbase + 16384 + off);
            }
            uint32_t bh[4][4], blr[4][4];
#pragma unroll
            for (int ng = 0; ng < 4; ++ng) {
                uint32_t row = b_row + ng * 16;
                uint32_t seg = (uint32_t)(s * 2) + b_sb;
                uint32_t off = (row << 7) + (seg << 4);
                off ^= (off >> 3) & 0x70;
                LDSM4(bh[ng],  sbase + 32768 + off);
                LDSM4(blr[ng], sbase + 49152 + off);
            }
#pragma unroll
            for (int mt = 0; mt < 2; ++mt) {
#pragma unroll
                for (int ng = 0; ng < 4; ++ng) {
                    float* d0 = acc[mt][2 * ng];
                    float* d1 = acc[mt][2 * ng + 1];
                    MMA16816(d0, ah[mt], bh[ng][0],  bh[ng][1]);
                    MMA16816(d0, ah[mt], blr[ng][0], blr[ng][1]);
                    MMA16816(d0, al[mt], bh[ng][0],  bh[ng][1]);
                    MMA16816(d1, ah[mt], bh[ng][2],  bh[ng][3]);
                    MMA16816(d1, ah[mt], blr[ng][2], blr[ng][3]);
                    MMA16816(d1, al[mt], bh[ng][2],  bh[ng][3]);
                }
            }
        }
        if (ct + 2 < C) { load_chunk(ct + 2, (ct + 2) % 3); CP_COMMIT; }
    }

    // ---- epilogue: registers -> global ----
    const int l4 = lane >> 2;
    const int l2 = (lane & 3) * 2;
#pragma unroll
    for (int mt = 0; mt < 2; ++mt) {
        const int m = m0 + wm * 32 + mt * 16 + l4;
        float bm0 = 0.f, bm8 = 0.f;
        if (bias && !bias_per_n) { bm0 = bias[m]; bm8 = bias[m + 8]; }
#pragma unroll
        for (int nt = 0; nt < 8; ++nt) {
            const int n = n0 + wn * 64 + nt * 8 + l2;
            float bn0 = 0.f, bn1 = 0.f;
            if (bias && bias_per_n) { bn0 = bias[n]; bn1 = bias[n + 1]; }
            const float* a4 = acc[mt][nt];
            float v00 = a4[0] * alpha, v01 = a4[1] * alpha;
            float v10 = a4[2] * alpha, v11 = a4[3] * alpha;
            if (bias) {
                if (bias_per_n) { v00 += bn0; v01 += bn1; v10 += bn0; v11 += bn1; }
                else            { v00 += bm0; v01 += bm0; v10 += bm8; v11 += bm8; }
            }
            if (OUT == 0) {
                float* d0 = Cf + b * sC + (ll)m * ldc + n;
                float* d1 = Cf + b * sC + (ll)(m + 8) * ldc + n;
                *reinterpret_cast<float2*>(d0) = make_float2(v00, v01);
                *reinterpret_cast<float2*>(d1) = make_float2(v10, v11);
            } else {
                bf16 h00 = __float2bfloat16_rn(v00), h01 = __float2bfloat16_rn(v01);
                bf16 h10 = __float2bfloat16_rn(v10), h11 = __float2bfloat16_rn(v11);
                bf16 l00 = __float2bfloat16_rn(v00 - __bfloat162float(h00));
                bf16 l01 = __float2bfloat16_rn(v01 - __bfloat162float(h01));
                bf16 l10 = __float2bfloat16_rn(v10 - __bfloat162float(h10));
                bf16 l11 = __float2bfloat16_rn(v11 - __bfloat162float(h11));
                ll o0 = b * sC + (ll)m * ldc + n;
                ll o1 = b * sC + (ll)(m + 8) * ldc + n;
                *reinterpret_cast<uint32_t*>(Chi + o0) = pack_bf(h00, h01);
                *reinterpret_cast<uint32_t*>(Chi + o1) = pack_bf(h10, h11);
                *reinterpret_cast<uint32_t*>(Clo + o0) = pack_bf(l00, l01);
                *reinterpret_cast<uint32_t*>(Clo + o1) = pack_bf(l10, l11);
            }
        }
    }
}

// ---------------------------------------------------------------------------
// fp32 -> (hi, lo) bf16 split, elementwise. n multiple of 1024.
// ---------------------------------------------------------------------------
__global__ __launch_bounds__(256) void split_kernel(
    const float* __restrict__ in, bf16* __restrict__ hi, bf16* __restrict__ lo)
{
    ll i = ((ll)blockIdx.x * 256 + threadIdx.x) * 4;
    float4 v = *reinterpret_cast<const float4*>(in + i);
    float vv[4] = {v.x, v.y, v.z, v.w};
#pragma unroll
    for (int q = 0; q < 4; ++q) {
        bf16 h = __float2bfloat16_rn(vv[q]);
        hi[i + q] = h;
        lo[i + q] = __float2bfloat16_rn(vv[q] - __bfloat162float(h));
    }
}

// ---------------------------------------------------------------------------
// Transpose + split: in (b, R, X) fp32 -> out (b, X, R) hi/lo bf16
// ---------------------------------------------------------------------------
__global__ __launch_bounds__(256) void transpose_split_kernel(
    const float* __restrict__ in, bf16* __restrict__ hi, bf16* __restrict__ lo,
    int R, int X)
{
    __shared__ float t[32][33];
    const ll b = blockIdx.z;
    const float* ib = in + b * (ll)R * X;
    const int x0 = blockIdx.x << 5, r0 = blockIdx.y << 5;
    const int tx = threadIdx.x & 31, ty = threadIdx.x >> 5;
#pragma unroll
    for (int i = 0; i < 4; ++i)
        t[ty + 8 * i][tx] = ib[(ll)(r0 + ty + 8 * i) * X + x0 + tx];
    __syncthreads();
    const ll ob = b * (ll)R * X;
#pragma unroll
    for (int i = 0; i < 4; ++i) {
        float v = t[tx][ty + 8 * i];
        ll o = ob + (ll)(x0 + ty + 8 * i) * R + r0 + tx;
        bf16 h = __float2bfloat16_rn(v);
        hi[o] = h;
        lo[o] = __float2bfloat16_rn(v - __bfloat162float(h));
    }
}

// ---------------------------------------------------------------------------
// Plain fp32 transpose: in (R, X) -> out (X, R)   (for ln_w / ln_b)
// ---------------------------------------------------------------------------
__global__ __launch_bounds__(256) void transpose_f32_kernel(
    const float* __restrict__ in, float* __restrict__ out, int R, int X)
{
    __shared__ float t[32][33];
    const int x0 = blockIdx.x << 5, r0 = blockIdx.y << 5;
    const int tx = threadIdx.x & 31, ty = threadIdx.x >> 5;
#pragma unroll
    for (int i = 0; i < 4; ++i)
        t[ty + 8 * i][tx] = in[(ll)(r0 + ty + 8 * i) * X + x0 + tx];
    __syncthreads();
#pragma unroll
    for (int i = 0; i < 4; ++i)
        out[(ll)(x0 + ty + 8 * i) * R + r0 + tx] = t[tx][ty + 8 * i];
}

// ---------------------------------------------------------------------------
// Softmax over L (=2048) + split write
// ---------------------------------------------------------------------------
__global__ __launch_bounds__(256) void softmax_split_kernel(
    const float* __restrict__ x, bf16* __restrict__ phi_, bf16* __restrict__ plo_)
{
    const ll row = blockIdx.x;
    const float* p = x + row * (ll)LL;
    const int tid = threadIdx.x;

    float v[8];
#pragma unroll
    for (int i = 0; i < 8; ++i) v[i] = p[tid + i * 256];

    float m = v[0];
#pragma unroll
    for (int i = 1; i < 8; ++i) m = fmaxf(m, v[i]);
#pragma unroll
    for (int o = 16; o > 0; o >>= 1) m = fmaxf(m, __shfl_xor_sync(0xffffffffu, m, o));
    __shared__ float sm[8];
    if ((tid & 31) == 0) sm[tid >> 5] = m;
    __syncthreads();
    float mx = sm[0];
#pragma unroll
    for (int i = 1; i < 8; ++i) mx = fmaxf(mx, sm[i]);

    float s = 0.f;
#pragma unroll
    for (int i = 0; i < 8; ++i) { v[i] = __expf(v[i] - mx); s += v[i]; }
#pragma unroll
    for (int o = 16; o > 0; o >>= 1) s += __shfl_xor_sync(0xffffffffu, s, o);
    __shared__ float ss[8];
    if ((tid & 31) == 0) ss[tid >> 5] = s;
    __syncthreads();
    float tot = 0.f;
#pragma unroll
    for (int i = 0; i < 8; ++i) tot += ss[i];
    float inv = 1.f / tot;
#pragma unroll
    for (int i = 0; i < 8; ++i) {
        float r = v[i] * inv;
        ll o = row * (ll)LL + tid + i * 256;
        bf16 h = __float2bfloat16_rn(r);
        phi_[o] = h;
        plo_[o] = __float2bfloat16_rn(r - __bfloat162float(h));
    }
}

// ---------------------------------------------------------------------------
// LayerNorm stats per batch over (S, LAT)
// ---------------------------------------------------------------------------
__global__ __launch_bounds__(512) void stats_kernel(
    const float* __restrict__ att, float2* __restrict__ stats)
{
    const int n = blockIdx.x;
    const float* x = att + (ll)n * LAT * SS;
    const int tid = threadIdx.x;
    float s = 0.f, s2 = 0.f;
    for (int i = tid; i < LAT * SS; i += 512) {
        float v = x[i];
        s += v; s2 += v * v;
    }
#pragma unroll
    for (int o = 16; o > 0; o >>= 1) {
        s  += __shfl_xor_sync(0xffffffffu, s,  o);
        s2 += __shfl_xor_sync(0xffffffffu, s2, o);
    }
    __shared__ float rs[16], rs2[16];
    if ((tid & 31) == 0) { rs[tid >> 5] = s; rs2[tid >> 5] = s2; }
    __syncthreads();
    if (tid == 0) {
        float S = 0.f, S2 = 0.f;
#pragma unroll
        for (int i = 0; i < 16; ++i) { S += rs[i]; S2 += rs2[i]; }
        const float invM = 1.f / (float)(LAT * SS);
        float mu = S * invM;
        float var = S2 * invM - mu * mu;
        stats[n] = make_float2(mu, rsqrtf(var + LN_EPS));
    }
}

// ---------------------------------------------------------------------------
// LN affine + ReLU + split; wT/bT are pre-transposed to (S, LAT)
// att/y layout (b, S, LAT); one block per (b, s) row
// ---------------------------------------------------------------------------
__global__ __launch_bounds__(128) void affine_relu_split_kernel(
    const float* __restrict__ att, const float* __restrict__ wT,
    const float* __restrict__ bT, const float2* __restrict__ stats,
    bf16* __restrict__ yhi, bf16* __restrict__ ylo)
{
    const ll row = blockIdx.x;              // b*SS + s
    const int b = (int)(row >> 9), s = (int)(row & 511);
    const float2 st = stats[b];
    const float* x = att + row * (ll)LAT;
    const float* w = wT + (ll)s * LAT;
    const float* bb = bT + (ll)s * LAT;
    const ll o = row * (ll)LAT;
#pragma unroll
    for (int i = 0; i < 4; ++i) {
        int lat = threadIdx.x + (i << 7);
        float v = fmaxf((x[lat] - st.x) * st.y * w[lat] + bb[lat], 0.f);
        bf16 h = __float2bfloat16_rn(v);
        yhi[o + lat] = h;
        ylo[o + lat] = __float2bfloat16_rn(v - __bfloat162float(h));
    }
}

// ---------------------------------------------------------------------------
// Launch
// ---------------------------------------------------------------------------
extern "C" void kernel_launch(void* const* d_in, const int* in_sizes, int n_in,
                              void* d_out, int out_size)
{
    const float* st_feat = (const float*)d_in[0];
    const float* lt_feat = (const float*)d_in[1];
    const float* w_st    = (const float*)d_in[2];
    const float* b_st    = (const float*)d_in[3];
    const float* w_lt    = (const float*)d_in[4];
    const float* b_lt    = (const float*)d_in[5];
    const float* w_g     = (const float*)d_in[6];
    const float* b_g     = (const float*)d_in[7];
    const float* ln_w    = (const float*)d_in[8];
    const float* ln_b    = (const float*)d_in[9];
    const float* w_out   = (const float*)d_in[10];
    const float* b_out   = (const float*)d_in[11];
    float* out = (float*)d_out;

    unsigned char* pool;
    cudaGetSymbolAddress((void**)&pool, g_pool);
    bf16* stT_hi   = (bf16*)(pool + O_STT_HI);
    bf16* stT_lo   = (bf16*)(pool + O_STT_LO);
    bf16* ltT_hi   = (bf16*)(pool + O_LTT_HI);
    bf16* ltT_lo   = (bf16*)(pool + O_LTT_LO);
    bf16* theta_hi = (bf16*)(pool + O_THETA_HI);
    bf16* theta_lo = (bf16*)(pool + O_THETA_LO);
    bf16* phi_hi   = (bf16*)(pool + O_PHI_HI);
    bf16* phi_lo   = (bf16*)(pool + O_PHI_LO);
    bf16* g_hi     = (bf16*)(pool + O_G_HI);
    bf16* g_lo     = (bf16*)(pool + O_G_LO);
    float* scores  = (float*)(pool + O_SCORE);
    bf16* p_hi     = (bf16*)(pool + O_P_HI);
    bf16* p_lo     = (bf16*)(pool + O_P_LO);
    float* att     = (float*)(pool + O_ATT);
    bf16* y_hi     = (bf16*)(pool + O_Y_HI);
    bf16* y_lo     = (bf16*)(pool + O_Y_LO);
    bf16* wst_hi   = (bf16*)(pool + O_WST_HI);
    bf16* wst_lo   = (bf16*)(pool + O_WST_LO);
    bf16* wlt_hi   = (bf16*)(pool + O_WLT_HI);
    bf16* wlt_lo   = (bf16*)(pool + O_WLT_LO);
    bf16* wg_hi    = (bf16*)(pool + O_WG_HI);
    bf16* wg_lo    = (bf16*)(pool + O_WG_LO);
    bf16* wout_hi  = (bf16*)(pool + O_WOUT_HI);
    bf16* wout_lo  = (bf16*)(pool + O_WOUT_LO);
    float* lnw_t   = (float*)(pool + O_LNW_T);
    float* lnb_t   = (float*)(pool + O_LNB_T);
    float2* stats  = (float2*)(pool + O_STATS);

    cudaFuncSetAttribute(mma_gemm<0>, cudaFuncAttributeMaxDynamicSharedMemorySize, SMEM_TOTAL);
    cudaFuncSetAttribute(mma_gemm<1>, cudaFuncAttributeMaxDynamicSharedMemorySize, SMEM_TOTAL);

    const float inv_sqrt_lat = 0.044194173824159216f;   // 1/sqrt(512)

    // --- operand conversion ---
    split_kernel<<<1024, 256>>>(w_st,  wst_hi,  wst_lo);    // 512x2048
    split_kernel<<<1024, 256>>>(w_lt,  wlt_hi,  wlt_lo);
    split_kernel<<<1024, 256>>>(w_g,   wg_hi,   wg_lo);
    split_kernel<<<1024, 256>>>(w_out, wout_hi, wout_lo);   // 2048x512
    transpose_split_kernel<<<dim3(SS / 32, C_ST / 32, NB), 256>>>(st_feat, stT_hi, stT_lo, C_ST, SS);
    transpose_split_kernel<<<dim3(LL / 32, C_LT / 32, NB), 256>>>(lt_feat, ltT_hi, ltT_lo, C_LT, LL);
    transpose_f32_kernel<<<dim3(SS / 32, LAT / 32), 256>>>(ln_w, lnw_t, LAT, SS);
    transpose_f32_kernel<<<dim3(SS / 32, LAT / 32), 256>>>(ln_b, lnb_t, LAT, SS);

    // --- G1: theta(s,lat) = stT(s,c) . w_st(lat,c) + b_st  -> split ---
    mma_gemm<1><<<dim3(LAT / 128, SS / 128, NB), 256, SMEM_TOTAL>>>(
        stT_hi, stT_lo, wst_hi, wst_lo, nullptr, theta_hi, theta_lo,
        C_ST, LAT, (ll)SS * C_ST, 0, (ll)SS * LAT, 1.f, b_st, 1);

    // --- G2: phi(l,lat) = ltT(l,c) . w_lt(lat,c) + b_lt  -> split ---
    mma_gemm<1><<<dim3(LAT / 128, LL / 128, NB), 256, SMEM_TOTAL>>>(
        ltT_hi, ltT_lo, wlt_hi, wlt_lo, nullptr, phi_hi, phi_lo,
        C_LT, LAT, (ll)LL * C_LT, 0, (ll)LL * LAT, 1.f, b_lt, 1);

    // --- G3: g(lat,l) = w_g(lat,c) . ltT(l,c) + b_g  -> split ---
    mma_gemm<1><<<dim3(LL / 128, LAT / 128, NB), 256, SMEM_TOTAL>>>(
        wg_hi, wg_lo, ltT_hi, ltT_lo, nullptr, g_hi, g_lo,
        C_LT, LL, 0, (ll)LL * C_LT, (ll)LAT * LL, 1.f, b_g, 0);

    // --- G4: scores(s,l) = theta(s,.) . phi(l,.) / sqrt(LAT)  -> fp32 ---
    mma_gemm<0><<<dim3(LL / 128, SS / 128, NB), 256, SMEM_TOTAL>>>(
        theta_hi, theta_lo, phi_hi, phi_lo, scores, nullptr, nullptr,
        LAT, LL, (ll)SS * LAT, (ll)LL * LAT, (ll)SS * LL, inv_sqrt_lat, nullptr, 0);

    // --- softmax over L + split ---
    softmax_split_kernel<<<NB * SS, 256>>>(scores, p_hi, p_lo);

    // --- G5: att(s,lat) = p(s,l) . g(lat,l)  -> fp32 ---
    mma_gemm<0><<<dim3(LAT / 128, SS / 128, NB), 256, SMEM_TOTAL>>>(
        p_hi, p_lo, g_hi, g_lo, att, nullptr, nullptr,
        LL, LAT, (ll)SS * LL, (ll)LAT * LL, (ll)SS * LAT, 1.f, nullptr, 0);

    // --- LayerNorm stats + affine + relu + split ---
    stats_kernel<<<NB, 512>>>(att, stats);
    affine_relu_split_kernel<<<NB * SS, 128>>>(att, lnw_t, lnb_t, stats, y_hi, y_lo);

    // --- G6: out(c,s) = w_out(c,lat) . y(s,lat) + b_out  -> fp32 (d_out) ---
    mma_gemm<0><<<dim3(SS / 128, C_ST / 128, NB), 256, SMEM_TOTAL>>>(
        wout_hi, wout_lo, y_hi, y_lo, out, nullptr, nullptr,
        LAT, SS, 0, (ll)SS * LAT, (ll)C_ST * SS, 1.f, b_out, 0);
}

// round 5
// speedup vs baseline: 3.1131x; 1.0456x over previous
#include <cuda_runtime.h>
#include <cuda_bf16.h>
#include <cstdint>
#include <math.h>

// ---------------------------------------------------------------------------
// Problem constants
// ---------------------------------------------------------------------------
#define NB    32
#define C_ST  2048
#define C_LT  2048
#define LAT   512
#define SS    512
#define LL    2048
#define LN_EPS 1e-5f

typedef long long ll;
typedef __nv_bfloat16 bf16;

// ---------------------------------------------------------------------------
// Scratch pool (single __device__ global; offsets in bytes, 256-aligned)
// ---------------------------------------------------------------------------
static constexpr ll SZ_STT   = (ll)NB * SS  * C_ST * 2;   // one bf16 array
static constexpr ll SZ_LTT   = (ll)NB * LL  * C_LT * 2;
static constexpr ll SZ_THETA = (ll)NB * SS  * LAT  * 2;
static constexpr ll SZ_PHI   = (ll)NB * LL  * LAT  * 2;
static constexpr ll SZ_G     = (ll)NB * LAT * LL   * 2;
static constexpr ll SZ_SCORE = (ll)NB * SS  * LL   * 4;   // fp32
static constexpr ll SZ_P     = (ll)NB * SS  * LL   * 2;
static constexpr ll SZ_ATT   = (ll)NB * SS  * LAT  * 4;   // fp32
static constexpr ll SZ_Y     = (ll)NB * SS  * LAT  * 2;
static constexpr ll SZ_W     = (ll)LAT * C_ST * 2;        // each weight bf16 array
static constexpr ll SZ_LN    = (ll)LAT * SS * 4;          // transposed ln param fp32

static constexpr ll O_STT_HI   = 0;
static constexpr ll O_STT_LO   = O_STT_HI   + SZ_STT;
static constexpr ll O_LTT_HI   = O_STT_LO   + SZ_STT;
static constexpr ll O_LTT_LO   = O_LTT_HI   + SZ_LTT;
static constexpr ll O_THETA_HI = O_LTT_LO   + SZ_LTT;
static constexpr ll O_THETA_LO = O_THETA_HI + SZ_THETA;
static constexpr ll O_PHI_HI   = O_THETA_LO + SZ_THETA;
static constexpr ll O_PHI_LO   = O_PHI_HI   + SZ_PHI;
static constexpr ll O_G_HI     = O_PHI_LO   + SZ_PHI;
static constexpr ll O_G_LO     = O_G_HI     + SZ_G;
static constexpr ll O_SCORE    = O_G_LO     + SZ_G;
static constexpr ll O_P_HI     = O_SCORE    + SZ_SCORE;
static constexpr ll O_P_LO     = O_P_HI     + SZ_P;
static constexpr ll O_ATT      = O_P_LO     + SZ_P;
static constexpr ll O_Y_HI     = O_ATT      + SZ_ATT;
static constexpr ll O_Y_LO     = O_Y_HI     + SZ_Y;
static constexpr ll O_WST_HI   = O_Y_LO     + SZ_Y;
static constexpr ll O_WST_LO   = O_WST_HI   + SZ_W;
static constexpr ll O_WLT_HI   = O_WST_LO   + SZ_W;
static constexpr ll O_WLT_LO   = O_WLT_HI   + SZ_W;
static constexpr ll O_WG_HI    = O_WLT_LO   + SZ_W;
static constexpr ll O_WG_LO    = O_WG_HI    + SZ_W;
static constexpr ll O_WOUT_HI  = O_WG_LO    + SZ_W;
static constexpr ll O_WOUT_LO  = O_WOUT_HI  + SZ_W;
static constexpr ll O_LNW_T    = O_WOUT_LO  + SZ_W;
static constexpr ll O_LNB_T    = O_LNW_T    + SZ_LN;
static constexpr ll O_STATS    = O_LNB_T    + SZ_LN;
static constexpr ll POOL_BYTES = O_STATS + 256;

__device__ __align__(256) unsigned char g_pool[POOL_BYTES];

// ---------------------------------------------------------------------------
// PTX helpers (sm_80-compatible path: ldmatrix + mma.sync + cp.async)
// ---------------------------------------------------------------------------
__device__ __forceinline__ uint32_t smem_u32(const void* p) {
    uint32_t a;
    asm("{ .reg .u64 t; cvta.to.shared.u64 t, %1; cvt.u32.u64 %0, t; }"
        : "=r"(a) : "l"(p));
    return a;
}
__device__ __forceinline__ void cpa16(uint32_t s, const void* g) {
    asm volatile("cp.async.cg.shared.global [%0], [%1], 16;" :: "r"(s), "l"(g) : "memory");
}
#define CP_COMMIT asm volatile("cp.async.commit_group;" ::: "memory")
#define CP_WAIT1  asm volatile("cp.async.wait_group 1;" ::: "memory")
#define CP_WAIT0  asm volatile("cp.async.wait_group 0;" ::: "memory")

#define LDSM4(r, addr) \
    asm volatile("ldmatrix.sync.aligned.m8n8.x4.shared.b16 {%0,%1,%2,%3}, [%4];" \
        : "=r"((r)[0]), "=r"((r)[1]), "=r"((r)[2]), "=r"((r)[3]) : "r"(addr))

#define MMA16816(d, a, b0, b1) \
    asm volatile("mma.sync.aligned.m16n8k16.row.col.f32.bf16.bf16.f32 " \
        "{%0,%1,%2,%3}, {%4,%5,%6,%7}, {%8,%9}, {%0,%1,%2,%3};" \
        : "+f"((d)[0]), "+f"((d)[1]), "+f"((d)[2]), "+f"((d)[3]) \
        : "r"((a)[0]), "r"((a)[1]), "r"((a)[2]), "r"((a)[3]), "r"(b0), "r"(b1))

__device__ __forceinline__ uint32_t pack_bf(bf16 a, bf16 b) {
    return (uint32_t)__bfloat16_as_ushort(a) | ((uint32_t)__bfloat16_as_ushort(b) << 16);
}

// ---------------------------------------------------------------------------
// Tensor-core GEMM (mma.sync bf16, split hi/lo 3-term):
//   C(m,n) = alpha * sum_k (Ahi+Alo)(m,k)*(Bhi+Blo)(n,k) + bias   [lo*lo dropped]
//   A, B K-major (lda=ldb=K). CTA tile M=128, N=256, K-chunk 64.
//   Warp grid 2(m) x 4(n); warp tile 64x64. 2-stage cp.async double buffer.
//   OUT=0: fp32 to Cf.  OUT=1: split hi/lo bf16 to Chi/Clo.
// Stage layout: Ahi[0,16K) Alo[16K,32K) Bhi[32K,64K) Blo[64K,96K)
// ---------------------------------------------------------------------------
static constexpr int STAGE_BYTES = 98304;
static constexpr int STAGES      = 2;
static constexpr int SMEM_TOTAL  = STAGES * STAGE_BYTES;   // 196608

template <int OUT>
__global__ __launch_bounds__(256) void mma_gemm(
    const bf16* __restrict__ Ahi, const bf16* __restrict__ Alo,
    const bf16* __restrict__ Bhi, const bf16* __restrict__ Blo,
    float* __restrict__ Cf, bf16* __restrict__ Chi, bf16* __restrict__ Clo,
    int K, int ldc, ll sA, ll sB, ll sC,
    float alpha, const float* __restrict__ bias, int bias_per_n)
{
    extern __shared__ __align__(1024) char smem[];
    const uint32_t sb = smem_u32(smem);
    const int tid  = threadIdx.x;
    const int wid  = tid >> 5, lane = tid & 31;
    const ll  b    = blockIdx.z;
    const int m0   = blockIdx.y << 7;
    const int n0   = blockIdx.x << 8;

    const bf16* Ah = Ahi + b * sA;
    const bf16* Al = Alo + b * sA;
    const bf16* Bh = Bhi + b * sB;
    const bf16* Bl = Blo + b * sB;

    const int C = K >> 6;

    auto load_chunk = [&](int ct, int stg) {
        const uint32_t base = sb + stg * STAGE_BYTES;
        const int kt = ct << 6;
#pragma unroll
        for (int i = 0; i < 4; ++i) {           // A: 128 rows x 128B (each half)
            int idx = tid + (i << 8);
            int row = idx >> 3, seg = idx & 7;
            ll  go  = (ll)(m0 + row) * K + kt + (seg << 3);
            uint32_t so = (uint32_t)((row << 7) + (seg << 4));
            so ^= (so >> 3) & 0x70;
            cpa16(base + so,         Ah + go);
            cpa16(base + 16384 + so, Al + go);
        }
#pragma unroll
        for (int i = 0; i < 8; ++i) {           // B: 256 rows x 128B (each half)
            int idx = tid + (i << 8);
            int row = idx >> 3, seg = idx & 7;
            ll  go  = (ll)(n0 + row) * K + kt + (seg << 3);
            uint32_t so = (uint32_t)((row << 7) + (seg << 4));
            so ^= (so >> 3) & 0x70;
            cpa16(base + 32768 + so, Bh + go);
            cpa16(base + 65536 + so, Bl + go);
        }
    };

    load_chunk(0, 0); CP_COMMIT;

    // warp tiling: 2 (m) x 4 (n); each warp 64(m) x 64(n)
    const int wm = wid >> 2, wn = wid & 3;
    float acc[4][8][4];
#pragma unroll
    for (int i = 0; i < 4; ++i)
#pragma unroll
        for (int j = 0; j < 8; ++j)
#pragma unroll
            for (int q = 0; q < 4; ++q) acc[i][j][q] = 0.f;

    // ldmatrix lane addressing (within tile, before swizzle)
    const uint32_t a_row = (uint32_t)(wm * 64 + (lane & 15));
    const uint32_t a_sb  = (uint32_t)(lane >> 4);            // +seg for k8-15
    const uint32_t b_row = (uint32_t)(wn * 64 + ((lane >> 4) << 3) + (lane & 7));
    const uint32_t b_sb  = (uint32_t)((lane >> 3) & 1);

    for (int ct = 0; ct < C; ++ct) {
        const uint32_t sbase = sb + (ct & 1) * STAGE_BYTES;
        if (ct + 1 < C) { load_chunk(ct + 1, (ct + 1) & 1); CP_COMMIT; CP_WAIT1; }
        else            { CP_WAIT0; }
        __syncthreads();

#pragma unroll
        for (int s = 0; s < 4; ++s) {           // 4 x k16 per chunk
            uint32_t ah[4][4], al4[4][4];
#pragma unroll
            for (int mt = 0; mt < 4; ++mt) {
                uint32_t row = a_row + mt * 16;
                uint32_t seg = (uint32_t)(s * 2) + a_sb;
                uint32_t off = (row << 7) + (seg << 4);
                off ^= (off >> 3) & 0x70;
                LDSM4(ah[mt],  sbase + off);
                LDSM4(al4[mt], sbase + 16384 + off);
            }
            uint32_t bh[4][4], bl4[4][4];
#pragma unroll
            for (int ng = 0; ng < 4; ++ng) {
                uint32_t row = b_row + ng * 16;
                uint32_t seg = (uint32_t)(s * 2) + b_sb;
                uint32_t off = (row << 7) + (seg << 4);
                off ^= (off >> 3) & 0x70;
                LDSM4(bh[ng],  sbase + 32768 + off);
                LDSM4(bl4[ng], sbase + 65536 + off);
            }
#pragma unroll
            for (int mt = 0; mt < 4; ++mt) {
#pragma unroll
                for (int ng = 0; ng < 4; ++ng) {
                    float* d0 = acc[mt][2 * ng];
                    float* d1 = acc[mt][2 * ng + 1];
                    MMA16816(d0, ah[mt],  bh[ng][0],  bh[ng][1]);
                    MMA16816(d0, ah[mt],  bl4[ng][0], bl4[ng][1]);
                    MMA16816(d0, al4[mt], bh[ng][0],  bh[ng][1]);
                    MMA16816(d1, ah[mt],  bh[ng][2],  bh[ng][3]);
                    MMA16816(d1, ah[mt],  bl4[ng][2], bl4[ng][3]);
                    MMA16816(d1, al4[mt], bh[ng][2],  bh[ng][3]);
                }
            }
        }
        __syncthreads();
    }

    // ---- epilogue: registers -> global ----
    const int l4 = lane >> 2;
    const int l2 = (lane & 3) * 2;
#pragma unroll
    for (int mt = 0; mt < 4; ++mt) {
        const int m = m0 + wm * 64 + mt * 16 + l4;
        float bm0 = 0.f, bm8 = 0.f;
        if (bias && !bias_per_n) { bm0 = bias[m]; bm8 = bias[m + 8]; }
#pragma unroll
        for (int nt = 0; nt < 8; ++nt) {
            const int n = n0 + wn * 64 + nt * 8 + l2;
            float bn0 = 0.f, bn1 = 0.f;
            if (bias && bias_per_n) { bn0 = bias[n]; bn1 = bias[n + 1]; }
            const float* a4 = acc[mt][nt];
            float v00 = a4[0] * alpha, v01 = a4[1] * alpha;
            float v10 = a4[2] * alpha, v11 = a4[3] * alpha;
            if (bias) {
                if (bias_per_n) { v00 += bn0; v01 += bn1; v10 += bn0; v11 += bn1; }
                else            { v00 += bm0; v01 += bm0; v10 += bm8; v11 += bm8; }
            }
            if (OUT == 0) {
                float* d0 = Cf + b * sC + (ll)m * ldc + n;
                float* d1 = Cf + b * sC + (ll)(m + 8) * ldc + n;
                *reinterpret_cast<float2*>(d0) = make_float2(v00, v01);
                *reinterpret_cast<float2*>(d1) = make_float2(v10, v11);
            } else {
                bf16 h00 = __float2bfloat16_rn(v00), h01 = __float2bfloat16_rn(v01);
                bf16 h10 = __float2bfloat16_rn(v10), h11 = __float2bfloat16_rn(v11);
                bf16 l00 = __float2bfloat16_rn(v00 - __bfloat162float(h00));
                bf16 l01 = __float2bfloat16_rn(v01 - __bfloat162float(h01));
                bf16 l10 = __float2bfloat16_rn(v10 - __bfloat162float(h10));
                bf16 l11 = __float2bfloat16_rn(v11 - __bfloat162float(h11));
                ll o0 = b * sC + (ll)m * ldc + n;
                ll o1 = b * sC + (ll)(m + 8) * ldc + n;
                *reinterpret_cast<uint32_t*>(Chi + o0) = pack_bf(h00, h01);
                *reinterpret_cast<uint32_t*>(Chi + o1) = pack_bf(h10, h11);
                *reinterpret_cast<uint32_t*>(Clo + o0) = pack_bf(l00, l01);
                *reinterpret_cast<uint32_t*>(Clo + o1) = pack_bf(l10, l11);
            }
        }
    }
}

// ---------------------------------------------------------------------------
// fp32 -> (hi, lo) bf16 split, elementwise. n multiple of 1024.
// ---------------------------------------------------------------------------
__global__ __launch_bounds__(256) void split_kernel(
    const float* __restrict__ in, bf16* __restrict__ hi, bf16* __restrict__ lo)
{
    ll i = ((ll)blockIdx.x * 256 + threadIdx.x) * 4;
    float4 v = *reinterpret_cast<const float4*>(in + i);
    float vv[4] = {v.x, v.y, v.z, v.w};
#pragma unroll
    for (int q = 0; q < 4; ++q) {
        bf16 h = __float2bfloat16_rn(vv[q]);
        hi[i + q] = h;
        lo[i + q] = __float2bfloat16_rn(vv[q] - __bfloat162float(h));
    }
}

// ---------------------------------------------------------------------------
// Transpose + split: in (b, R, X) fp32 -> out (b, X, R) hi/lo bf16
// ---------------------------------------------------------------------------
__global__ __launch_bounds__(256) void transpose_split_kernel(
    const float* __restrict__ in, bf16* __restrict__ hi, bf16* __restrict__ lo,
    int R, int X)
{
    __shared__ float t[32][33];
    const ll b = blockIdx.z;
    const float* ib = in + b * (ll)R * X;
    const int x0 = blockIdx.x << 5, r0 = blockIdx.y << 5;
    const int tx = threadIdx.x & 31, ty = threadIdx.x >> 5;
#pragma unroll
    for (int i = 0; i < 4; ++i)
        t[ty + 8 * i][tx] = ib[(ll)(r0 + ty + 8 * i) * X + x0 + tx];
    __syncthreads();
    const ll ob = b * (ll)R * X;
#pragma unroll
    for (int i = 0; i < 4; ++i) {
        float v = t[tx][ty + 8 * i];
        ll o = ob + (ll)(x0 + ty + 8 * i) * R + r0 + tx;
        bf16 h = __float2bfloat16_rn(v);
        hi[o] = h;
        lo[o] = __float2bfloat16_rn(v - __bfloat162float(h));
    }
}

// ---------------------------------------------------------------------------
// Plain fp32 transpose: in (R, X) -> out (X, R)   (for ln_w / ln_b)
// ---------------------------------------------------------------------------
__global__ __launch_bounds__(256) void transpose_f32_kernel(
    const float* __restrict__ in, float* __restrict__ out, int R, int X)
{
    __shared__ float t[32][33];
    const int x0 = blockIdx.x << 5, r0 = blockIdx.y << 5;
    const int tx = threadIdx.x & 31, ty = threadIdx.x >> 5;
#pragma unroll
    for (int i = 0; i < 4; ++i)
        t[ty + 8 * i][tx] = in[(ll)(r0 + ty + 8 * i) * X + x0 + tx];
    __syncthreads();
#pragma unroll
    for (int i = 0; i < 4; ++i)
        out[(ll)(x0 + ty + 8 * i) * R + r0 + tx] = t[tx][ty + 8 * i];
}

// ---------------------------------------------------------------------------
// Softmax over L (=2048) + split write
// ---------------------------------------------------------------------------
__global__ __launch_bounds__(256) void softmax_split_kernel(
    const float* __restrict__ x, bf16* __restrict__ phi_, bf16* __restrict__ plo_)
{
    const ll row = blockIdx.x;
    const float* p = x + row * (ll)LL;
    const int tid = threadIdx.x;

    float v[8];
#pragma unroll
    for (int i = 0; i < 8; ++i) v[i] = p[tid + i * 256];

    float m = v[0];
#pragma unroll
    for (int i = 1; i < 8; ++i) m = fmaxf(m, v[i]);
#pragma unroll
    for (int o = 16; o > 0; o >>= 1) m = fmaxf(m, __shfl_xor_sync(0xffffffffu, m, o));
    __shared__ float sm[8];
    if ((tid & 31) == 0) sm[tid >> 5] = m;
    __syncthreads();
    float mx = sm[0];
#pragma unroll
    for (int i = 1; i < 8; ++i) mx = fmaxf(mx, sm[i]);

    float s = 0.f;
#pragma unroll
    for (int i = 0; i < 8; ++i) { v[i] = __expf(v[i] - mx); s += v[i]; }
#pragma unroll
    for (int o = 16; o > 0; o >>= 1) s += __shfl_xor_sync(0xffffffffu, s, o);
    __shared__ float ss[8];
    if ((tid & 31) == 0) ss[tid >> 5] = s;
    __syncthreads();
    float tot = 0.f;
#pragma unroll
    for (int i = 0; i < 8; ++i) tot += ss[i];
    float inv = 1.f / tot;
#pragma unroll
    for (int i = 0; i < 8; ++i) {
        float r = v[i] * inv;
        ll o = row * (ll)LL + tid + i * 256;
        bf16 h = __float2bfloat16_rn(r);
        phi_[o] = h;
        plo_[o] = __float2bfloat16_rn(r - __bfloat162float(h));
    }
}

// ---------------------------------------------------------------------------
// LayerNorm stats per batch over (S, LAT)
// ---------------------------------------------------------------------------
__global__ __launch_bounds__(512) void stats_kernel(
    const float* __restrict__ att, float2* __restrict__ stats)
{
    const int n = blockIdx.x;
    const float* x = att + (ll)n * LAT * SS;
    const int tid = threadIdx.x;
    float s = 0.f, s2 = 0.f;
    for (int i = tid; i < LAT * SS; i += 512) {
        float v = x[i];
        s += v; s2 += v * v;
    }
#pragma unroll
    for (int o = 16; o > 0; o >>= 1) {
        s  += __shfl_xor_sync(0xffffffffu, s,  o);
        s2 += __shfl_xor_sync(0xffffffffu, s2, o);
    }
    __shared__ float rs[16], rs2[16];
    if ((tid & 31) == 0) { rs[tid >> 5] = s; rs2[tid >> 5] = s2; }
    __syncthreads();
    if (tid == 0) {
        float S = 0.f, S2 = 0.f;
#pragma unroll
        for (int i = 0; i < 16; ++i) { S += rs[i]; S2 += rs2[i]; }
        const float invM = 1.f / (float)(LAT * SS);
        float mu = S * invM;
        float var = S2 * invM - mu * mu;
        stats[n] = make_float2(mu, rsqrtf(var + LN_EPS));
    }
}

// ---------------------------------------------------------------------------
// LN affine + ReLU + split; wT/bT are pre-transposed to (S, LAT)
// att/y layout (b, S, LAT); one block per (b, s) row
// ---------------------------------------------------------------------------
__global__ __launch_bounds__(128) void affine_relu_split_kernel(
    const float* __restrict__ att, const float* __restrict__ wT,
    const float* __restrict__ bT, const float2* __restrict__ stats,
    bf16* __restrict__ yhi, bf16* __restrict__ ylo)
{
    const ll row = blockIdx.x;              // b*SS + s
    const int b = (int)(row >> 9), s = (int)(row & 511);
    const float2 st = stats[b];
    const float* x = att + row * (ll)LAT;
    const float* w = wT + (ll)s * LAT;
    const float* bb = bT + (ll)s * LAT;
    const ll o = row * (ll)LAT;
#pragma unroll
    for (int i = 0; i < 4; ++i) {
        int lat = threadIdx.x + (i << 7);
        float v = fmaxf((x[lat] - st.x) * st.y * w[lat] + bb[lat], 0.f);
        bf16 h = __float2bfloat16_rn(v);
        yhi[o + lat] = h;
        ylo[o + lat] = __float2bfloat16_rn(v - __bfloat162float(h));
    }
}

// ---------------------------------------------------------------------------
// Launch
// ---------------------------------------------------------------------------
extern "C" void kernel_launch(void* const* d_in, const int* in_sizes, int n_in,
                              void* d_out, int out_size)
{
    const float* st_feat = (const float*)d_in[0];
    const float* lt_feat = (const float*)d_in[1];
    const float* w_st    = (const float*)d_in[2];
    const float* b_st    = (const float*)d_in[3];
    const float* w_lt    = (const float*)d_in[4];
    const float* b_lt    = (const float*)d_in[5];
    const float* w_g     = (const float*)d_in[6];
    const float* b_g     = (const float*)d_in[7];
    const float* ln_w    = (const float*)d_in[8];
    const float* ln_b    = (const float*)d_in[9];
    const float* w_out   = (const float*)d_in[10];
    const float* b_out   = (const float*)d_in[11];
    float* out = (float*)d_out;

    unsigned char* pool;
    cudaGetSymbolAddress((void**)&pool, g_pool);
    bf16* stT_hi   = (bf16*)(pool + O_STT_HI);
    bf16* stT_lo   = (bf16*)(pool + O_STT_LO);
    bf16* ltT_hi   = (bf16*)(pool + O_LTT_HI);
    bf16* ltT_lo   = (bf16*)(pool + O_LTT_LO);
    bf16* theta_hi = (bf16*)(pool + O_THETA_HI);
    bf16* theta_lo = (bf16*)(pool + O_THETA_LO);
    bf16* phi_hi   = (bf16*)(pool + O_PHI_HI);
    bf16* phi_lo   = (bf16*)(pool + O_PHI_LO);
    bf16* g_hi     = (bf16*)(pool + O_G_HI);
    bf16* g_lo     = (bf16*)(pool + O_G_LO);
    float* scores  = (float*)(pool + O_SCORE);
    bf16* p_hi     = (bf16*)(pool + O_P_HI);
    bf16* p_lo     = (bf16*)(pool + O_P_LO);
    float* att     = (float*)(pool + O_ATT);
    bf16* y_hi     = (bf16*)(pool + O_Y_HI);
    bf16* y_lo     = (bf16*)(pool + O_Y_LO);
    bf16* wst_hi   = (bf16*)(pool + O_WST_HI);
    bf16* wst_lo   = (bf16*)(pool + O_WST_LO);
    bf16* wlt_hi   = (bf16*)(pool + O_WLT_HI);
    bf16* wlt_lo   = (bf16*)(pool + O_WLT_LO);
    bf16* wg_hi    = (bf16*)(pool + O_WG_HI);
    bf16* wg_lo    = (bf16*)(pool + O_WG_LO);
    bf16* wout_hi  = (bf16*)(pool + O_WOUT_HI);
    bf16* wout_lo  = (bf16*)(pool + O_WOUT_LO);
    float* lnw_t   = (float*)(pool + O_LNW_T);
    float* lnb_t   = (float*)(pool + O_LNB_T);
    float2* stats  = (float2*)(pool + O_STATS);

    cudaFuncSetAttribute(mma_gemm<0>, cudaFuncAttributeMaxDynamicSharedMemorySize, SMEM_TOTAL);
    cudaFuncSetAttribute(mma_gemm<1>, cudaFuncAttributeMaxDynamicSharedMemorySize, SMEM_TOTAL);

    const float inv_sqrt_lat = 0.044194173824159216f;   // 1/sqrt(512)

    // --- operand conversion ---
    split_kernel<<<1024, 256>>>(w_st,  wst_hi,  wst_lo);    // 512x2048
    split_kernel<<<1024, 256>>>(w_lt,  wlt_hi,  wlt_lo);
    split_kernel<<<1024, 256>>>(w_g,   wg_hi,   wg_lo);
    split_kernel<<<1024, 256>>>(w_out, wout_hi, wout_lo);   // 2048x512
    transpose_split_kernel<<<dim3(SS / 32, C_ST / 32, NB), 256>>>(st_feat, stT_hi, stT_lo, C_ST, SS);
    transpose_split_kernel<<<dim3(LL / 32, C_LT / 32, NB), 256>>>(lt_feat, ltT_hi, ltT_lo, C_LT, LL);
    transpose_f32_kernel<<<dim3(SS / 32, LAT / 32), 256>>>(ln_w, lnw_t, LAT, SS);
    transpose_f32_kernel<<<dim3(SS / 32, LAT / 32), 256>>>(ln_b, lnb_t, LAT, SS);

    // --- G1: theta(s,lat) = stT(s,c) . w_st(lat,c) + b_st  -> split ---
    mma_gemm<1><<<dim3(LAT / 256, SS / 128, NB), 256, SMEM_TOTAL>>>(
        stT_hi, stT_lo, wst_hi, wst_lo, nullptr, theta_hi, theta_lo,
        C_ST, LAT, (ll)SS * C_ST, 0, (ll)SS * LAT, 1.f, b_st, 1);

    // --- G2: phi(l,lat) = ltT(l,c) . w_lt(lat,c) + b_lt  -> split ---
    mma_gemm<1><<<dim3(LAT / 256, LL / 128, NB), 256, SMEM_TOTAL>>>(
        ltT_hi, ltT_lo, wlt_hi, wlt_lo, nullptr, phi_hi, phi_lo,
        C_LT, LAT, (ll)LL * C_LT, 0, (ll)LL * LAT, 1.f, b_lt, 1);

    // --- G3: g(lat,l) = w_g(lat,c) . ltT(l,c) + b_g  -> split ---
    mma_gemm<1><<<dim3(LL / 256, LAT / 128, NB), 256, SMEM_TOTAL>>>(
        wg_hi, wg_lo, ltT_hi, ltT_lo, nullptr, g_hi, g_lo,
        C_LT, LL, 0, (ll)LL * C_LT, (ll)LAT * LL, 1.f, b_g, 0);

    // --- G4: scores(s,l) = theta(s,.) . phi(l,.) / sqrt(LAT)  -> fp32 ---
    mma_gemm<0><<<dim3(LL / 256, SS / 128, NB), 256, SMEM_TOTAL>>>(
        theta_hi, theta_lo, phi_hi, phi_lo, scores, nullptr, nullptr,
        LAT, LL, (ll)SS * LAT, (ll)LL * LAT, (ll)SS * LL, inv_sqrt_lat, nullptr, 0);

    // --- softmax over L + split ---
    softmax_split_kernel<<<NB * SS, 256>>>(scores, p_hi, p_lo);

    // --- G5: att(s,lat) = p(s,l) . g(lat,l)  -> fp32 ---
    mma_gemm<0><<<dim3(LAT / 256, SS / 128, NB), 256, SMEM_TOTAL>>>(
        p_hi, p_lo, g_hi, g_lo, att, nullptr, nullptr,
        LL, LAT, (ll)SS * LL, (ll)LAT * LL, (ll)SS * LAT, 1.f, nullptr, 0);

    // --- LayerNorm stats + affine + relu + split ---
    stats_kernel<<<NB, 512>>>(att, stats);
    affine_relu_split_kernel<<<NB * SS, 128>>>(att, lnw_t, lnb_t, stats, y_hi, y_lo);

    // --- G6: out(c,s) = w_out(c,lat) . y(s,lat) + b_out  -> fp32 (d_out) ---
    mma_gemm<0><<<dim3(SS / 256, C_ST / 128, NB), 256, SMEM_TOTAL>>>(
        wout_hi, wout_lo, y_hi, y_lo, out, nullptr, nullptr,
        LAT, SS, 0, (ll)SS * LAT, (ll)C_ST * SS, 1.f, b_out, 0);
}

// round 6
// speedup vs baseline: 3.1621x; 1.0157x over previous
#include <cuda_runtime.h>
#include <cuda_bf16.h>
#include <cstdint>
#include <math.h>

// ---------------------------------------------------------------------------
// Problem constants
// ---------------------------------------------------------------------------
#define NB    32
#define C_ST  2048
#define C_LT  2048
#define LAT   512
#define SS    512
#define LL    2048
#define LN_EPS 1e-5f

typedef long long ll;
typedef __nv_bfloat16 bf16;

// ---------------------------------------------------------------------------
// Scratch pool (single __device__ global; offsets in bytes, 256-aligned)
// ---------------------------------------------------------------------------
static constexpr ll SZ_STT   = (ll)NB * SS  * C_ST * 2;   // one bf16 array
static constexpr ll SZ_LTT   = (ll)NB * LL  * C_LT * 2;
static constexpr ll SZ_THETA = (ll)NB * SS  * LAT  * 2;
static constexpr ll SZ_PHI   = (ll)NB * LL  * LAT  * 2;
static constexpr ll SZ_G     = (ll)NB * LAT * LL   * 2;
static constexpr ll SZ_SCORE = (ll)NB * SS  * LL   * 4;   // fp32
static constexpr ll SZ_P     = (ll)NB * SS  * LL   * 2;
static constexpr ll SZ_ATT   = (ll)NB * SS  * LAT  * 4;   // fp32
static constexpr ll SZ_Y     = (ll)NB * SS  * LAT  * 2;
static constexpr ll SZ_W     = (ll)LAT * C_ST * 2;        // each weight bf16 array
static constexpr ll SZ_LN    = (ll)LAT * SS * 4;          // transposed ln param fp32

static constexpr ll O_STT_HI   = 0;
static constexpr ll O_STT_LO   = O_STT_HI   + SZ_STT;
static constexpr ll O_LTT_HI   = O_STT_LO   + SZ_STT;
static constexpr ll O_LTT_LO   = O_LTT_HI   + SZ_LTT;
static constexpr ll O_THETA_HI = O_LTT_LO   + SZ_LTT;
static constexpr ll O_THETA_LO = O_THETA_HI + SZ_THETA;
static constexpr ll O_PHI_HI   = O_THETA_LO + SZ_THETA;
static constexpr ll O_PHI_LO   = O_PHI_HI   + SZ_PHI;
static constexpr ll O_G_HI     = O_PHI_LO   + SZ_PHI;
static constexpr ll O_G_LO     = O_G_HI     + SZ_G;
static constexpr ll O_SCORE    = O_G_LO     + SZ_G;
static constexpr ll O_P_HI     = O_SCORE    + SZ_SCORE;
static constexpr ll O_P_LO     = O_P_HI     + SZ_P;
static constexpr ll O_ATT      = O_P_LO     + SZ_P;
static constexpr ll O_Y_HI     = O_ATT      + SZ_ATT;
static constexpr ll O_Y_LO     = O_Y_HI     + SZ_Y;
static constexpr ll O_WST_HI   = O_Y_LO     + SZ_Y;
static constexpr ll O_WST_LO   = O_WST_HI   + SZ_W;
static constexpr ll O_WLT_HI   = O_WST_LO   + SZ_W;
static constexpr ll O_WLT_LO   = O_WLT_HI   + SZ_W;
static constexpr ll O_WG_HI    = O_WLT_LO   + SZ_W;
static constexpr ll O_WG_LO    = O_WG_HI    + SZ_W;
static constexpr ll O_WOUT_HI  = O_WG_LO    + SZ_W;
static constexpr ll O_WOUT_LO  = O_WOUT_HI  + SZ_W;
static constexpr ll O_LNW_T    = O_WOUT_LO  + SZ_W;
static constexpr ll O_LNB_T    = O_LNW_T    + SZ_LN;
static constexpr ll O_STATS    = O_LNB_T    + SZ_LN;
static constexpr ll POOL_BYTES = O_STATS + 256;

__device__ __align__(256) unsigned char g_pool[POOL_BYTES];

// ---------------------------------------------------------------------------
// PTX helpers (sm_80-compatible path: ldmatrix + mma.sync + cp.async)
// ---------------------------------------------------------------------------
__device__ __forceinline__ uint32_t smem_u32(const void* p) {
    uint32_t a;
    asm("{ .reg .u64 t; cvta.to.shared.u64 t, %1; cvt.u32.u64 %0, t; }"
        : "=r"(a) : "l"(p));
    return a;
}
__device__ __forceinline__ void cpa16(uint32_t s, const void* g) {
    asm volatile("cp.async.cg.shared.global [%0], [%1], 16;" :: "r"(s), "l"(g) : "memory");
}
#define CP_COMMIT asm volatile("cp.async.commit_group;" ::: "memory")
#define CP_WAIT1  asm volatile("cp.async.wait_group 1;" ::: "memory")
#define CP_WAIT0  asm volatile("cp.async.wait_group 0;" ::: "memory")

#define LDSM4(r, addr) \
    asm volatile("ldmatrix.sync.aligned.m8n8.x4.shared.b16 {%0,%1,%2,%3}, [%4];" \
        : "=r"((r)[0]), "=r"((r)[1]), "=r"((r)[2]), "=r"((r)[3]) : "r"(addr))

#define MMA16816(d, a, b0, b1) \
    asm volatile("mma.sync.aligned.m16n8k16.row.col.f32.bf16.bf16.f32 " \
        "{%0,%1,%2,%3}, {%4,%5,%6,%7}, {%8,%9}, {%0,%1,%2,%3};" \
        : "+f"((d)[0]), "+f"((d)[1]), "+f"((d)[2]), "+f"((d)[3]) \
        : "r"((a)[0]), "r"((a)[1]), "r"((a)[2]), "r"((a)[3]), "r"(b0), "r"(b1))

__device__ __forceinline__ uint32_t pack_bf(bf16 a, bf16 b) {
    return (uint32_t)__bfloat16_as_ushort(a) | ((uint32_t)__bfloat16_as_ushort(b) << 16);
}
__device__ __forceinline__ void split1(float v, bf16& h, bf16& l) {
    h = __float2bfloat16_rn(v);
    l = __float2bfloat16_rn(v - __bfloat162float(h));
}

// ---------------------------------------------------------------------------
// Tensor-core GEMM (mma.sync bf16, split hi/lo 3-term):
//   C(m,n) = alpha * sum_k (Ahi+Alo)(m,k)*(Bhi+Blo)(n,k) + bias   [lo*lo dropped]
//   A, B K-major (lda=ldb=K). CTA tile M=128, N=256, K-chunk 64.
//   Warp grid 2(m) x 4(n); warp tile 64x64. 2-stage cp.async double buffer.
//   OUT=0: fp32 to Cf.  OUT=1: split hi/lo bf16 to Chi/Clo.
// Stage layout: Ahi[0,16K) Alo[16K,32K) Bhi[32K,64K) Blo[64K,96K)
// ---------------------------------------------------------------------------
static constexpr int STAGE_BYTES = 98304;
static constexpr int STAGES      = 2;
static constexpr int SMEM_TOTAL  = STAGES * STAGE_BYTES;   // 196608

template <int OUT>
__global__ __launch_bounds__(256) void mma_gemm(
    const bf16* __restrict__ Ahi, const bf16* __restrict__ Alo,
    const bf16* __restrict__ Bhi, const bf16* __restrict__ Blo,
    float* __restrict__ Cf, bf16* __restrict__ Chi, bf16* __restrict__ Clo,
    int K, int ldc, ll sA, ll sB, ll sC,
    float alpha, const float* __restrict__ bias, int bias_per_n)
{
    extern __shared__ __align__(1024) char smem[];
    const uint32_t sb = smem_u32(smem);
    const int tid  = threadIdx.x;
    const int wid  = tid >> 5, lane = tid & 31;
    const ll  b    = blockIdx.z;
    const int m0   = blockIdx.y << 7;
    const int n0   = blockIdx.x << 8;

    const bf16* Ah = Ahi + b * sA;
    const bf16* Al = Alo + b * sA;
    const bf16* Bh = Bhi + b * sB;
    const bf16* Bl = Blo + b * sB;

    const int C = K >> 6;

    auto load_chunk = [&](int ct, int stg) {
        const uint32_t base = sb + stg * STAGE_BYTES;
        const int kt = ct << 6;
#pragma unroll
        for (int i = 0; i < 4; ++i) {           // A: 128 rows x 128B (each half)
            int idx = tid + (i << 8);
            int row = idx >> 3, seg = idx & 7;
            ll  go  = (ll)(m0 + row) * K + kt + (seg << 3);
            uint32_t so = (uint32_t)((row << 7) + (seg << 4));
            so ^= (so >> 3) & 0x70;
            cpa16(base + so,         Ah + go);
            cpa16(base + 16384 + so, Al + go);
        }
#pragma unroll
        for (int i = 0; i < 8; ++i) {           // B: 256 rows x 128B (each half)
            int idx = tid + (i << 8);
            int row = idx >> 3, seg = idx & 7;
            ll  go  = (ll)(n0 + row) * K + kt + (seg << 3);
            uint32_t so = (uint32_t)((row << 7) + (seg << 4));
            so ^= (so >> 3) & 0x70;
            cpa16(base + 32768 + so, Bh + go);
            cpa16(base + 65536 + so, Bl + go);
        }
    };

    load_chunk(0, 0); CP_COMMIT;

    // warp tiling: 2 (m) x 4 (n); each warp 64(m) x 64(n)
    const int wm = wid >> 2, wn = wid & 3;
    float acc[4][8][4];
#pragma unroll
    for (int i = 0; i < 4; ++i)
#pragma unroll
        for (int j = 0; j < 8; ++j)
#pragma unroll
            for (int q = 0; q < 4; ++q) acc[i][j][q] = 0.f;

    // ldmatrix lane addressing (within tile, before swizzle)
    const uint32_t a_row = (uint32_t)(wm * 64 + (lane & 15));
    const uint32_t a_sb  = (uint32_t)(lane >> 4);            // +seg for k8-15
    const uint32_t b_row = (uint32_t)(wn * 64 + ((lane >> 4) << 3) + (lane & 7));
    const uint32_t b_sb  = (uint32_t)((lane >> 3) & 1);

    for (int ct = 0; ct < C; ++ct) {
        const uint32_t sbase = sb + (ct & 1) * STAGE_BYTES;
        if (ct + 1 < C) { load_chunk(ct + 1, (ct + 1) & 1); CP_COMMIT; CP_WAIT1; }
        else            { CP_WAIT0; }
        __syncthreads();

#pragma unroll
        for (int s = 0; s < 4; ++s) {           // 4 x k16 per chunk
            uint32_t ah[4][4], al4[4][4];
#pragma unroll
            for (int mt = 0; mt < 4; ++mt) {
                uint32_t row = a_row + mt * 16;
                uint32_t seg = (uint32_t)(s * 2) + a_sb;
                uint32_t off = (row << 7) + (seg << 4);
                off ^= (off >> 3) & 0x70;
                LDSM4(ah[mt],  sbase + off);
                LDSM4(al4[mt], sbase + 16384 + off);
            }
            uint32_t bh[4][4], bl4[4][4];
#pragma unroll
            for (int ng = 0; ng < 4; ++ng) {
                uint32_t row = b_row + ng * 16;
                uint32_t seg = (uint32_t)(s * 2) + b_sb;
                uint32_t off = (row << 7) + (seg << 4);
                off ^= (off >> 3) & 0x70;
                LDSM4(bh[ng],  sbase + 32768 + off);
                LDSM4(bl4[ng], sbase + 65536 + off);
            }
#pragma unroll
            for (int mt = 0; mt < 4; ++mt) {
#pragma unroll
                for (int ng = 0; ng < 4; ++ng) {
                    float* d0 = acc[mt][2 * ng];
                    float* d1 = acc[mt][2 * ng + 1];
                    MMA16816(d0, ah[mt],  bh[ng][0],  bh[ng][1]);
                    MMA16816(d0, ah[mt],  bl4[ng][0], bl4[ng][1]);
                    MMA16816(d0, al4[mt], bh[ng][0],  bh[ng][1]);
                    MMA16816(d1, ah[mt],  bh[ng][2],  bh[ng][3]);
                    MMA16816(d1, ah[mt],  bl4[ng][2], bl4[ng][3]);
                    MMA16816(d1, al4[mt], bh[ng][2],  bh[ng][3]);
                }
            }
        }
        __syncthreads();
    }

    // ---- epilogue: registers -> global ----
    const int l4 = lane >> 2;
    const int l2 = (lane & 3) * 2;
#pragma unroll
    for (int mt = 0; mt < 4; ++mt) {
        const int m = m0 + wm * 64 + mt * 16 + l4;
        float bm0 = 0.f, bm8 = 0.f;
        if (bias && !bias_per_n) { bm0 = bias[m]; bm8 = bias[m + 8]; }
#pragma unroll
        for (int nt = 0; nt < 8; ++nt) {
            const int n = n0 + wn * 64 + nt * 8 + l2;
            float bn0 = 0.f, bn1 = 0.f;
            if (bias && bias_per_n) { bn0 = bias[n]; bn1 = bias[n + 1]; }
            const float* a4 = acc[mt][nt];
            float v00 = a4[0] * alpha, v01 = a4[1] * alpha;
            float v10 = a4[2] * alpha, v11 = a4[3] * alpha;
            if (bias) {
                if (bias_per_n) { v00 += bn0; v01 += bn1; v10 += bn0; v11 += bn1; }
                else            { v00 += bm0; v01 += bm0; v10 += bm8; v11 += bm8; }
            }
            if (OUT == 0) {
                float* d0 = Cf + b * sC + (ll)m * ldc + n;
                float* d1 = Cf + b * sC + (ll)(m + 8) * ldc + n;
                *reinterpret_cast<float2*>(d0) = make_float2(v00, v01);
                *reinterpret_cast<float2*>(d1) = make_float2(v10, v11);
            } else {
                bf16 h00, h01, h10, h11, l00, l01, l10, l11;
                split1(v00, h00, l00); split1(v01, h01, l01);
                split1(v10, h10, l10); split1(v11, h11, l11);
                ll o0 = b * sC + (ll)m * ldc + n;
                ll o1 = b * sC + (ll)(m + 8) * ldc + n;
                *reinterpret_cast<uint32_t*>(Chi + o0) = pack_bf(h00, h01);
                *reinterpret_cast<uint32_t*>(Chi + o1) = pack_bf(h10, h11);
                *reinterpret_cast<uint32_t*>(Clo + o0) = pack_bf(l00, l01);
                *reinterpret_cast<uint32_t*>(Clo + o1) = pack_bf(l10, l11);
            }
        }
    }
}

// ---------------------------------------------------------------------------
// fp32 -> (hi, lo) bf16 split, elementwise, 8 elems/thread, 16B stores.
// n must be a multiple of 2048.
// ---------------------------------------------------------------------------
__global__ __launch_bounds__(256) void split_kernel(
    const float* __restrict__ in, bf16* __restrict__ hi, bf16* __restrict__ lo)
{
    ll i = ((ll)blockIdx.x * 256 + threadIdx.x) * 8;
    float4 a = *reinterpret_cast<const float4*>(in + i);
    float4 c = *reinterpret_cast<const float4*>(in + i + 4);
    float v[8] = {a.x, a.y, a.z, a.w, c.x, c.y, c.z, c.w};
    uint32_t hp[4], lp[4];
#pragma unroll
    for (int q = 0; q < 4; ++q) {
        bf16 h0, l0, h1, l1;
        split1(v[2*q], h0, l0); split1(v[2*q+1], h1, l1);
        hp[q] = pack_bf(h0, h1); lp[q] = pack_bf(l0, l1);
    }
    *reinterpret_cast<uint4*>(hi + i) = make_uint4(hp[0], hp[1], hp[2], hp[3]);
    *reinterpret_cast<uint4*>(lo + i) = make_uint4(lp[0], lp[1], lp[2], lp[3]);
}

// ---------------------------------------------------------------------------
// Transpose + split: in (b, R, X) fp32 -> out (b, X, R) hi/lo bf16
// 64x64 tiles, float4 reads, 8B packed bf16 writes (128B per out row).
// ---------------------------------------------------------------------------
__global__ __launch_bounds__(256) void transpose_split_kernel(
    const float* __restrict__ in, bf16* __restrict__ hi, bf16* __restrict__ lo,
    int R, int X)
{
    __shared__ float t[64][65];
    const ll b = blockIdx.z;
    const float* ib = in + b * (ll)R * X;
    const int x0 = blockIdx.x << 6, r0 = blockIdx.y << 6;
    const int tx = threadIdx.x & 15;        // 16 x float4 = 64 columns
    const int ty = threadIdx.x >> 4;        // 16 rows per pass
#pragma unroll
    for (int i = 0; i < 4; ++i) {
        int r = ty + 16 * i;
        float4 v = *reinterpret_cast<const float4*>(
            ib + (ll)(r0 + r) * X + x0 + tx * 4);
        t[r][tx * 4 + 0] = v.x; t[r][tx * 4 + 1] = v.y;
        t[r][tx * 4 + 2] = v.z; t[r][tx * 4 + 3] = v.w;
    }
    __syncthreads();
    const ll ob = b * (ll)R * X;
#pragma unroll
    for (int i = 0; i < 4; ++i) {
        int xr = ty + 16 * i;
        float w0 = t[tx * 4 + 0][xr];
        float w1 = t[tx * 4 + 1][xr];
        float w2 = t[tx * 4 + 2][xr];
        float w3 = t[tx * 4 + 3][xr];
        bf16 h0, l0, h1, l1, h2, l2, h3, l3;
        split1(w0, h0, l0); split1(w1, h1, l1);
        split1(w2, h2, l2); split1(w3, h3, l3);
        ll o = ob + (ll)(x0 + xr) * R + r0 + tx * 4;
        *reinterpret_cast<uint2*>(hi + o) = make_uint2(pack_bf(h0, h1), pack_bf(h2, h3));
        *reinterpret_cast<uint2*>(lo + o) = make_uint2(pack_bf(l0, l1), pack_bf(l2, l3));
    }
}

// ---------------------------------------------------------------------------
// Plain fp32 transpose: in (R, X) -> out (X, R)   (for ln_w / ln_b)
// ---------------------------------------------------------------------------
__global__ __launch_bounds__(256) void transpose_f32_kernel(
    const float* __restrict__ in, float* __restrict__ out, int R, int X)
{
    __shared__ float t[32][33];
    const int x0 = blockIdx.x << 5, r0 = blockIdx.y << 5;
    const int tx = threadIdx.x & 31, ty = threadIdx.x >> 5;
#pragma unroll
    for (int i = 0; i < 4; ++i)
        t[ty + 8 * i][tx] = in[(ll)(r0 + ty + 8 * i) * X + x0 + tx];
    __syncthreads();
#pragma unroll
    for (int i = 0; i < 4; ++i)
        out[(ll)(x0 + ty + 8 * i) * R + r0 + tx] = t[tx][ty + 8 * i];
}

// ---------------------------------------------------------------------------
// Softmax over L (=2048) + split write (packed 16B stores).
// One 256-thread block per row; each thread owns 8 consecutive elements.
// ---------------------------------------------------------------------------
__global__ __launch_bounds__(256) void softmax_split_kernel(
    const float* __restrict__ x, bf16* __restrict__ phi_, bf16* __restrict__ plo_)
{
    const ll row = blockIdx.x;
    const int tid = threadIdx.x;
    const float* p = x + row * (ll)LL + tid * 8;

    float4 a = *reinterpret_cast<const float4*>(p);
    float4 c = *reinterpret_cast<const float4*>(p + 4);
    float v[8] = {a.x, a.y, a.z, a.w, c.x, c.y, c.z, c.w};

    float m = v[0];
#pragma unroll
    for (int i = 1; i < 8; ++i) m = fmaxf(m, v[i]);
#pragma unroll
    for (int o = 16; o > 0; o >>= 1) m = fmaxf(m, __shfl_xor_sync(0xffffffffu, m, o));
    __shared__ float sm[8];
    if ((tid & 31) == 0) sm[tid >> 5] = m;
    __syncthreads();
    float mx = sm[0];
#pragma unroll
    for (int i = 1; i < 8; ++i) mx = fmaxf(mx, sm[i]);

    float s = 0.f;
#pragma unroll
    for (int i = 0; i < 8; ++i) { v[i] = __expf(v[i] - mx); s += v[i]; }
#pragma unroll
    for (int o = 16; o > 0; o >>= 1) s += __shfl_xor_sync(0xffffffffu, s, o);
    __shared__ float ss[8];
    if ((tid & 31) == 0) ss[tid >> 5] = s;
    __syncthreads();
    float tot = 0.f;
#pragma unroll
    for (int i = 0; i < 8; ++i) tot += ss[i];
    float inv = 1.f / tot;

    uint32_t hp[4], lp[4];
#pragma unroll
    for (int q = 0; q < 4; ++q) {
        float r0 = v[2*q] * inv, r1 = v[2*q+1] * inv;
        bf16 h0, l0, h1, l1;
        split1(r0, h0, l0); split1(r1, h1, l1);
        hp[q] = pack_bf(h0, h1); lp[q] = pack_bf(l0, l1);
    }
    ll o = row * (ll)LL + tid * 8;
    *reinterpret_cast<uint4*>(phi_ + o) = make_uint4(hp[0], hp[1], hp[2], hp[3]);
    *reinterpret_cast<uint4*>(plo_ + o) = make_uint4(lp[0], lp[1], lp[2], lp[3]);
}

// ---------------------------------------------------------------------------
// LayerNorm stats per batch over (S, LAT)
// ---------------------------------------------------------------------------
__global__ __launch_bounds__(512) void stats_kernel(
    const float* __restrict__ att, float2* __restrict__ stats)
{
    const int n = blockIdx.x;
    const float* x = att + (ll)n * LAT * SS;
    const int tid = threadIdx.x;
    float s = 0.f, s2 = 0.f;
    for (int i = tid * 4; i < LAT * SS; i += 512 * 4) {
        float4 v = *reinterpret_cast<const float4*>(x + i);
        s  += v.x + v.y + v.z + v.w;
        s2 += v.x * v.x + v.y * v.y + v.z * v.z + v.w * v.w;
    }
#pragma unroll
    for (int o = 16; o > 0; o >>= 1) {
        s  += __shfl_xor_sync(0xffffffffu, s,  o);
        s2 += __shfl_xor_sync(0xffffffffu, s2, o);
    }
    __shared__ float rs[16], rs2[16];
    if ((tid & 31) == 0) { rs[tid >> 5] = s; rs2[tid >> 5] = s2; }
    __syncthreads();
    if (tid == 0) {
        float S = 0.f, S2 = 0.f;
#pragma unroll
        for (int i = 0; i < 16; ++i) { S += rs[i]; S2 += rs2[i]; }
        const float invM = 1.f / (float)(LAT * SS);
        float mu = S * invM;
        float var = S2 * invM - mu * mu;
        stats[n] = make_float2(mu, rsqrtf(var + LN_EPS));
    }
}

// ---------------------------------------------------------------------------
// LN affine + ReLU + split; wT/bT pre-transposed to (S, LAT).
// att/y layout (b, S, LAT). 256-thread block handles 4 rows; 8 elems/thread.
// ---------------------------------------------------------------------------
__global__ __launch_bounds__(256) void affine_relu_split_kernel(
    const float* __restrict__ att, const float* __restrict__ wT,
    const float* __restrict__ bT, const float2* __restrict__ stats,
    bf16* __restrict__ yhi, bf16* __restrict__ ylo)
{
    const int r = threadIdx.x >> 6;               // 0..3
    const int c = (threadIdx.x & 63) * 8;         // 0..504
    const ll row = (ll)blockIdx.x * 4 + r;        // b*SS + s
    const int b = (int)(row >> 9), s = (int)(row & 511);
    const float2 st = stats[b];
    const float* xx = att + row * (ll)LAT + c;
    const float* ww = wT + (ll)s * LAT + c;
    const float* bb = bT + (ll)s * LAT + c;

    float4 x0 = *reinterpret_cast<const float4*>(xx);
    float4 x1 = *reinterpret_cast<const float4*>(xx + 4);
    float4 w0 = *reinterpret_cast<const float4*>(ww);
    float4 w1 = *reinterpret_cast<const float4*>(ww + 4);
    float4 b0 = *reinterpret_cast<const float4*>(bb);
    float4 b1 = *reinterpret_cast<const float4*>(bb + 4);
    float xv[8] = {x0.x, x0.y, x0.z, x0.w, x1.x, x1.y, x1.z, x1.w};
    float wv[8] = {w0.x, w0.y, w0.z, w0.w, w1.x, w1.y, w1.z, w1.w};
    float bv[8] = {b0.x, b0.y, b0.z, b0.w, b1.x, b1.y, b1.z, b1.w};

    uint32_t hp[4], lp[4];
#pragma unroll
    for (int q = 0; q < 4; ++q) {
        float v0 = fmaxf((xv[2*q]   - st.x) * st.y * wv[2*q]   + bv[2*q],   0.f);
        float v1 = fmaxf((xv[2*q+1] - st.x) * st.y * wv[2*q+1] + bv[2*q+1], 0.f);
        bf16 h0, l0, h1, l1;
        split1(v0, h0, l0); split1(v1, h1, l1);
        hp[q] = pack_bf(h0, h1); lp[q] = pack_bf(l0, l1);
    }
    ll o = row * (ll)LAT + c;
    *reinterpret_cast<uint4*>(yhi + o) = make_uint4(hp[0], hp[1], hp[2], hp[3]);
    *reinterpret_cast<uint4*>(ylo + o) = make_uint4(lp[0], lp[1], lp[2], lp[3]);
}

// ---------------------------------------------------------------------------
// Launch
// ---------------------------------------------------------------------------
extern "C" void kernel_launch(void* const* d_in, const int* in_sizes, int n_in,
                              void* d_out, int out_size)
{
    const float* st_feat = (const float*)d_in[0];
    const float* lt_feat = (const float*)d_in[1];
    const float* w_st    = (const float*)d_in[2];
    const float* b_st    = (const float*)d_in[3];
    const float* w_lt    = (const float*)d_in[4];
    const float* b_lt    = (const float*)d_in[5];
    const float* w_g     = (const float*)d_in[6];
    const float* b_g     = (const float*)d_in[7];
    const float* ln_w    = (const float*)d_in[8];
    const float* ln_b    = (const float*)d_in[9];
    const float* w_out   = (const float*)d_in[10];
    const float* b_out   = (const float*)d_in[11];
    float* out = (float*)d_out;

    unsigned char* pool;
    cudaGetSymbolAddress((void**)&pool, g_pool);
    bf16* stT_hi   = (bf16*)(pool + O_STT_HI);
    bf16* stT_lo   = (bf16*)(pool + O_STT_LO);
    bf16* ltT_hi   = (bf16*)(pool + O_LTT_HI);
    bf16* ltT_lo   = (bf16*)(pool + O_LTT_LO);
    bf16* theta_hi = (bf16*)(pool + O_THETA_HI);
    bf16* theta_lo = (bf16*)(pool + O_THETA_LO);
    bf16* phi_hi   = (bf16*)(pool + O_PHI_HI);
    bf16* phi_lo   = (bf16*)(pool + O_PHI_LO);
    bf16* g_hi     = (bf16*)(pool + O_G_HI);
    bf16* g_lo     = (bf16*)(pool + O_G_LO);
    float* scores  = (float*)(pool + O_SCORE);
    bf16* p_hi     = (bf16*)(pool + O_P_HI);
    bf16* p_lo     = (bf16*)(pool + O_P_LO);
    float* att     = (float*)(pool + O_ATT);
    bf16* y_hi     = (bf16*)(pool + O_Y_HI);
    bf16* y_lo     = (bf16*)(pool + O_Y_LO);
    bf16* wst_hi   = (bf16*)(pool + O_WST_HI);
    bf16* wst_lo   = (bf16*)(pool + O_WST_LO);
    bf16* wlt_hi   = (bf16*)(pool + O_WLT_HI);
    bf16* wlt_lo   = (bf16*)(pool + O_WLT_LO);
    bf16* wg_hi    = (bf16*)(pool + O_WG_HI);
    bf16* wg_lo    = (bf16*)(pool + O_WG_LO);
    bf16* wout_hi  = (bf16*)(pool + O_WOUT_HI);
    bf16* wout_lo  = (bf16*)(pool + O_WOUT_LO);
    float* lnw_t   = (float*)(pool + O_LNW_T);
    float* lnb_t   = (float*)(pool + O_LNB_T);
    float2* stats  = (float2*)(pool + O_STATS);

    cudaFuncSetAttribute(mma_gemm<0>, cudaFuncAttributeMaxDynamicSharedMemorySize, SMEM_TOTAL);
    cudaFuncSetAttribute(mma_gemm<1>, cudaFuncAttributeMaxDynamicSharedMemorySize, SMEM_TOTAL);

    const float inv_sqrt_lat = 0.044194173824159216f;   // 1/sqrt(512)

    // --- operand conversion ---
    split_kernel<<<512, 256>>>(w_st,  wst_hi,  wst_lo);    // 512x2048
    split_kernel<<<512, 256>>>(w_lt,  wlt_hi,  wlt_lo);
    split_kernel<<<512, 256>>>(w_g,   wg_hi,   wg_lo);
    split_kernel<<<512, 256>>>(w_out, wout_hi, wout_lo);   // 2048x512
    transpose_split_kernel<<<dim3(SS / 64, C_ST / 64, NB), 256>>>(st_feat, stT_hi, stT_lo, C_ST, SS);
    transpose_split_kernel<<<dim3(LL / 64, C_LT / 64, NB), 256>>>(lt_feat, ltT_hi, ltT_lo, C_LT, LL);
    transpose_f32_kernel<<<dim3(SS / 32, LAT / 32), 256>>>(ln_w, lnw_t, LAT, SS);
    transpose_f32_kernel<<<dim3(SS / 32, LAT / 32), 256>>>(ln_b, lnb_t, LAT, SS);

    // --- G1: theta(s,lat) = stT(s,c) . w_st(lat,c) + b_st  -> split ---
    mma_gemm<1><<<dim3(LAT / 256, SS / 128, NB), 256, SMEM_TOTAL>>>(
        stT_hi, stT_lo, wst_hi, wst_lo, nullptr, theta_hi, theta_lo,
        C_ST, LAT, (ll)SS * C_ST, 0, (ll)SS * LAT, 1.f, b_st, 1);

    // --- G2: phi(l,lat) = ltT(l,c) . w_lt(lat,c) + b_lt  -> split ---
    mma_gemm<1><<<dim3(LAT / 256, LL / 128, NB), 256, SMEM_TOTAL>>>(
        ltT_hi, ltT_lo, wlt_hi, wlt_lo, nullptr, phi_hi, phi_lo,
        C_LT, LAT, (ll)LL * C_LT, 0, (ll)LL * LAT, 1.f, b_lt, 1);

    // --- G3: g(lat,l) = w_g(lat,c) . ltT(l,c) + b_g  -> split ---
    mma_gemm<1><<<dim3(LL / 256, LAT / 128, NB), 256, SMEM_TOTAL>>>(
        wg_hi, wg_lo, ltT_hi, ltT_lo, nullptr, g_hi, g_lo,
        C_LT, LL, 0, (ll)LL * C_LT, (ll)LAT * LL, 1.f, b_g, 0);

    // --- G4: scores(s,l) = theta(s,.) . phi(l,.) / sqrt(LAT)  -> fp32 ---
    mma_gemm<0><<<dim3(LL / 256, SS / 128, NB), 256, SMEM_TOTAL>>>(
        theta_hi, theta_lo, phi_hi, phi_lo, scores, nullptr, nullptr,
        LAT, LL, (ll)SS * LAT, (ll)LL * LAT, (ll)SS * LL, inv_sqrt_lat, nullptr, 0);

    // --- softmax over L + split ---
    softmax_split_kernel<<<NB * SS, 256>>>(scores, p_hi, p_lo);

    // --- G5: att(s,lat) = p(s,l) . g(lat,l)  -> fp32 ---
    mma_gemm<0><<<dim3(LAT / 256, SS / 128, NB), 256, SMEM_TOTAL>>>(
        p_hi, p_lo, g_hi, g_lo, att, nullptr, nullptr,
        LL, LAT, (ll)SS * LL, (ll)LAT * LL, (ll)SS * LAT, 1.f, nullptr, 0);

    // --- LayerNorm stats + affine + relu + split ---
    stats_kernel<<<NB, 512>>>(att, stats);
    affine_relu_split_kernel<<<NB * SS / 4, 256>>>(att, lnw_t, lnb_t, stats, y_hi, y_lo);

    // --- G6: out(c,s) = w_out(c,lat) . y(s,lat) + b_out  -> fp32 (d_out) ---
    mma_gemm<0><<<dim3(SS / 256, C_ST / 128, NB), 256, SMEM_TOTAL>>>(
        wout_hi, wout_lo, y_hi, y_lo, out, nullptr, nullptr,
        LAT, SS, 0, (ll)SS * LAT, (ll)C_ST * SS, 1.f, b_out, 0);
}